// round 1
// baseline (speedup 1.0000x reference)
#include <cuda_runtime.h>
#include <cstdint>

#define B_   16
#define T_   2048
#define I_   1024
#define H_   1024
#define G_   3072
#define NCTA 128
#define COLS 24          // g-columns per CTA in recurrent kernel
#define WST  1026        // padded smem row stride (floats) to break bank conflicts

// ---------------- scratch (static device memory; no allocation) ----------------
__device__ float        d_proj[100663296ULL];   // 32768 x 3072 fp32 (x_rz | x_n after LN)
__device__ float        d_hh[B_ * G_];          // per-step hidden GEMM result
__device__ float        d_hbuf[2][B_ * H_];     // double-buffered hidden state
__device__ float        d_means[T_ * 32];       // [t][grp(2)][b(16)] column-sum accumulators
__device__ unsigned int d_bar[2 * T_];          // one counter per grid barrier

// ---------------- init: zero barrier counters + mean accumulators, load h0 ----------------
__global__ void __launch_bounds__(256) init_kernel(const float* __restrict__ h0) {
    int idx = blockIdx.x * blockDim.x + threadIdx.x;
    if (idx < 2 * T_)    d_bar[idx]   = 0u;
    if (idx < T_ * 32)   d_means[idx] = 0.f;
    if (idx < B_ * H_)   d_hbuf[0][idx] = h0[idx];
}

// ---------------- Phase A: proj[bt][g] = sum_i xs[bt][i] * w_ih[g][i] ----------------
// 128x128x16 tile, 256 threads, 8x8 per-thread microtile, fp32.
__global__ void __launch_bounds__(256) gemm_proj(const float* __restrict__ A,
                                                 const float* __restrict__ W) {
    __shared__ float As[16 * 132];
    __shared__ float Bs[16 * 132];
    const int tid = threadIdx.x;
    const int tm = blockIdx.y * 128;     // bt tile
    const int tn = blockIdx.x * 128;     // g tile
    const int ty = tid >> 4, tx = tid & 15;
    float acc[8][8];
#pragma unroll
    for (int i = 0; i < 8; i++)
#pragma unroll
        for (int j = 0; j < 8; j++) acc[i][j] = 0.f;

    for (int k0 = 0; k0 < 1024; k0 += 16) {
#pragma unroll
        for (int v = 0; v < 2; v++) {
            int idx = tid + v * 256;           // 0..511
            int r   = idx >> 2;                // 0..127
            int kq  = (idx & 3) << 2;          // 0,4,8,12
            float4 a = *(const float4*)(A + (size_t)(tm + r) * 1024 + k0 + kq);
            As[(kq + 0) * 132 + r] = a.x;
            As[(kq + 1) * 132 + r] = a.y;
            As[(kq + 2) * 132 + r] = a.z;
            As[(kq + 3) * 132 + r] = a.w;
            float4 b = *(const float4*)(W + (size_t)(tn + r) * 1024 + k0 + kq);
            Bs[(kq + 0) * 132 + r] = b.x;
            Bs[(kq + 1) * 132 + r] = b.y;
            Bs[(kq + 2) * 132 + r] = b.z;
            Bs[(kq + 3) * 132 + r] = b.w;
        }
        __syncthreads();
#pragma unroll
        for (int k = 0; k < 16; k++) {
            float a[8], b[8];
            *(float4*)(a)     = *(const float4*)(As + k * 132 + ty * 8);
            *(float4*)(a + 4) = *(const float4*)(As + k * 132 + ty * 8 + 4);
            *(float4*)(b)     = *(const float4*)(Bs + k * 132 + tx * 8);
            *(float4*)(b + 4) = *(const float4*)(Bs + k * 132 + tx * 8 + 4);
#pragma unroll
            for (int i = 0; i < 8; i++)
#pragma unroll
                for (int j = 0; j < 8; j++) acc[i][j] += a[i] * b[j];
        }
        __syncthreads();
    }
#pragma unroll
    for (int i = 0; i < 8; i++) {
        size_t row = (size_t)(tm + ty * 8 + i) * 3072 + tn + tx * 8;
        *(float4*)(d_proj + row)     = make_float4(acc[i][0], acc[i][1], acc[i][2], acc[i][3]);
        *(float4*)(d_proj + row + 4) = make_float4(acc[i][4], acc[i][5], acc[i][6], acc[i][7]);
    }
}

// ---------------- block reduce helper (sum, sumsq) over 256 threads ----------------
__device__ __forceinline__ float2 block_reduce2(float s, float s2, float* sm) {
#pragma unroll
    for (int o = 16; o; o >>= 1) {
        s  += __shfl_down_sync(0xffffffffu, s,  o);
        s2 += __shfl_down_sync(0xffffffffu, s2, o);
    }
    int w = threadIdx.x >> 5, l = threadIdx.x & 31;
    if (l == 0) { sm[w] = s; sm[8 + w] = s2; }
    __syncthreads();
    if (threadIdx.x < 32) {
        s  = (l < 8) ? sm[l]     : 0.f;
        s2 = (l < 8) ? sm[8 + l] : 0.f;
#pragma unroll
        for (int o = 4; o; o >>= 1) {
            s  += __shfl_down_sync(0xffffffffu, s,  o);
            s2 += __shfl_down_sync(0xffffffffu, s2, o);
        }
        if (l == 0) { sm[16] = s; sm[17] = s2; }
    }
    __syncthreads();
    return make_float2(sm[16], sm[17]);
}

// ---------------- Phase B: LN_x in place (var with N-1 divisor) ----------------
__global__ void __launch_bounds__(256) ln_x_kernel(const float* __restrict__ gamma,
                                                   const float* __restrict__ beta) {
    __shared__ float sm[18];
    float* row = d_proj + (size_t)blockIdx.x * 3072;
    const int tid = threadIdx.x;

    // group rz: 2048 elements
    float v[8];
    float s = 0.f, s2 = 0.f;
#pragma unroll
    for (int i = 0; i < 8; i++) {
        float x = row[tid + (i << 8)];
        v[i] = x; s += x; s2 += x * x;
    }
    float2 r = block_reduce2(s, s2, sm);
    {
        float mean = r.x * (1.f / 2048.f);
        float var  = (r.y - 2048.f * mean * mean) * (1.f / 2047.f);
        float rstd = rsqrtf(var);
#pragma unroll
        for (int i = 0; i < 8; i++) {
            int c = tid + (i << 8);
            row[c] = gamma[c] * (v[i] - mean) * rstd + beta[c];
        }
    }
    __syncthreads();

    // group n: 1024 elements
    float vn[4];
    s = 0.f; s2 = 0.f;
#pragma unroll
    for (int i = 0; i < 4; i++) {
        float x = row[2048 + tid + (i << 8)];
        vn[i] = x; s += x; s2 += x * x;
    }
    r = block_reduce2(s, s2, sm);
    {
        float mean = r.x * (1.f / 1024.f);
        float var  = (r.y - 1024.f * mean * mean) * (1.f / 1023.f);
        float rstd = rsqrtf(var);
#pragma unroll
        for (int i = 0; i < 4; i++) {
            int c = 2048 + tid + (i << 8);
            row[c] = gamma[c] * (vn[i] - mean) * rstd + beta[c];
        }
    }
}

// ---------------- grid barrier (counter per barrier, reset by init_kernel) ----------------
__device__ __forceinline__ void grid_barrier(int k) {
    __syncthreads();
    if (threadIdx.x == 0) {
        __threadfence();
        unsigned arrived = atomicAdd(&d_bar[k], 1u) + 1u;
        if (arrived < NCTA) {
            volatile unsigned* p = &d_bar[k];
            while (*p < NCTA) { __nanosleep(32); }
        }
    }
    __syncthreads();
}

// ---------------- Phase C: persistent recurrent kernel ----------------
__global__ void __launch_bounds__(256, 1) gru_rec(const float* __restrict__ w_hh,
                                                  const float* __restrict__ b_hh,
                                                  const float* __restrict__ gamma_hh,
                                                  float* __restrict__ out) {
    extern __shared__ float smf[];
    float* w_s  = smf;                     // COLS * WST
    float* h_s  = w_s + COLS * WST;        // 16 * WST
    float* red  = h_s + 16 * WST;          // 8 * 384
    float* ssum = red + 8 * 384;           // 32: [grp][b]

    const int cta  = blockIdx.x;
    const int tid  = threadIdx.x;
    const int c0   = cta * COLS;
    const int warp = tid >> 5, lane = tid & 31;
    const int lb   = lane >> 3, lc = lane & 7;   // 4 x 8 lane grid

    // stage w_hh slice (24 x 1024) into smem once
    for (int i = tid; i < COLS * 256; i += 256) {
        int c  = i >> 8;
        int kq = (i & 255) << 2;
        float4 vv = *(const float4*)(w_hh + (size_t)(c0 + c) * 1024 + kq);
        w_s[c * WST + kq + 0] = vv.x;
        w_s[c * WST + kq + 1] = vv.y;
        w_s[c * WST + kq + 2] = vv.z;
        w_s[c * WST + kq + 3] = vv.w;
    }

    for (int t = 0; t < T_; t++) {
        const float* hb = d_hbuf[t & 1];
        // stage h (16 x 1024) into smem; L1-bypass (written by other SMs last step)
        for (int i = tid; i < 4096; i += 256) {
            int b  = i >> 8;
            int kq = (i & 255) << 2;
            float4 vv = __ldcg((const float4*)(hb + b * 1024 + kq));
            h_s[b * WST + kq + 0] = vv.x;
            h_s[b * WST + kq + 1] = vv.y;
            h_s[b * WST + kq + 2] = vv.z;
            h_s[b * WST + kq + 3] = vv.w;
        }
        if (tid < 32) ssum[tid] = 0.f;
        __syncthreads();

        // warp k-split GEMM: out tile 16(b) x 24(c); per-lane 4b x 3c
        float acc[4][3];
#pragma unroll
        for (int i = 0; i < 4; i++)
#pragma unroll
            for (int j = 0; j < 3; j++) acc[i][j] = 0.f;

        const float* hp = h_s + (lb * 4) * WST + (warp << 7);
        const float* wp = w_s + (lc * 3) * WST + (warp << 7);
#pragma unroll 8
        for (int kk = 0; kk < 128; kk++) {
            float h0v = hp[kk];
            float h1v = hp[WST + kk];
            float h2v = hp[2 * WST + kk];
            float h3v = hp[3 * WST + kk];
            float w0v = wp[kk];
            float w1v = wp[WST + kk];
            float w2v = wp[2 * WST + kk];
            acc[0][0] += h0v * w0v; acc[0][1] += h0v * w1v; acc[0][2] += h0v * w2v;
            acc[1][0] += h1v * w0v; acc[1][1] += h1v * w1v; acc[1][2] += h1v * w2v;
            acc[2][0] += h2v * w0v; acc[2][1] += h2v * w1v; acc[2][2] += h2v * w2v;
            acc[3][0] += h3v * w0v; acc[3][1] += h3v * w1v; acc[3][2] += h3v * w2v;
        }
#pragma unroll
        for (int i = 0; i < 4; i++)
#pragma unroll
            for (int j = 0; j < 3; j++)
                red[warp * 384 + (lb * 4 + i) * 24 + lc * 3 + j] = acc[i][j];
        __syncthreads();

        // cross-warp reduce, write hh, accumulate per-(grp,b) column sums
        for (int o = tid; o < 384; o += 256) {
            float s = 0.f;
#pragma unroll
            for (int w = 0; w < 8; w++) s += red[w * 384 + o];
            int b  = o / 24;
            int c  = o - b * 24;
            int gc = c0 + c;
            d_hh[b * G_ + gc] = s;
            atomicAdd(&ssum[((gc >= 2048) ? 16 : 0) + b], s);
        }
        __syncthreads();
        if (tid < 32) atomicAdd(&d_means[t * 32 + tid], ssum[tid]);

        grid_barrier(2 * t);

        // gate + state update: 16384 units over 128 CTAs
        if (tid < 128) {
            int b = cta >> 3;
            int j = ((cta & 7) << 7) + tid;
            float mrz = __ldcg(&d_means[t * 32 + b])      * (1.f / 2048.f);
            float mn  = __ldcg(&d_means[t * 32 + 16 + b]) * (1.f / 1024.f);
            float hr  = __ldcg(&d_hh[b * G_ + j]);
            float hz  = __ldcg(&d_hh[b * G_ + 1024 + j]);
            float hn  = __ldcg(&d_hh[b * G_ + 2048 + j]);
            float lnr = gamma_hh[j]        * (hr - mrz) + b_hh[j];
            float lnz = gamma_hh[1024 + j] * (hz - mrz) + b_hh[1024 + j];
            float lnn = gamma_hh[2048 + j] * (hn - mn)  + b_hh[2048 + j];
            size_t bt = (size_t)b * T_ + t;
            const float* xr = d_proj + bt * 3072;
            float rg   = 1.f / (1.f + expf(-(xr[j] + lnr)));
            float zg   = 1.f / (1.f + expf(-(xr[1024 + j] + lnz)));
            float ng   = tanhf(xr[2048 + j] + rg * lnn);
            float hold = __ldcg(&hb[b * 1024 + j]);
            float hnew = (1.f - zg) * ng + zg * hold;
            d_hbuf[(t + 1) & 1][b * 1024 + j] = hnew;
            out[bt * 1024 + j] = hnew;
            if (t == T_ - 1) out[(size_t)B_ * T_ * H_ + b * 1024 + j] = hnew;
        }
        grid_barrier(2 * t + 1);
    }
}

// ---------------- launch ----------------
extern "C" void kernel_launch(void* const* d_in, const int* in_sizes, int n_in,
                              void* d_out, int out_size) {
    const float* xs   = (const float*)d_in[0];
    const float* h0   = (const float*)d_in[1];
    const float* w_ih = (const float*)d_in[2];
    const float* w_hh = (const float*)d_in[3];
    const float* b_ih = (const float*)d_in[4];
    const float* b_hh = (const float*)d_in[5];
    const float* g_ih = (const float*)d_in[6];
    const float* g_hh = (const float*)d_in[7];
    float* out = (float*)d_out;

    const int SMEM_REC = (COLS * WST + 16 * WST + 8 * 384 + 32) * (int)sizeof(float);
    cudaFuncSetAttribute(gru_rec, cudaFuncAttributeMaxDynamicSharedMemorySize, SMEM_REC);

    init_kernel<<<256, 256>>>(h0);
    dim3 g(G_ / 128, (B_ * T_) / 128);   // (24, 256)
    gemm_proj<<<g, 256>>>(xs, w_ih);
    ln_x_kernel<<<B_ * T_, 256>>>(g_ih, b_ih);
    gru_rec<<<NCTA, 256, SMEM_REC>>>(w_hh, b_hh, g_hh, out);
}

// round 3
// speedup vs baseline: 1.2583x; 1.2583x over previous
#include <cuda_runtime.h>
#include <cuda_bf16.h>
#include <cstdint>

#define B_   16
#define T_   2048
#define G_   3072
#define NCTA 128
#define COLS 24

// ---------------- scratch (static device memory; no allocation) ----------------
__device__ float         d_proj[100663296ULL];   // 32768 x 3072 fp32
__device__ float         d_hh[B_ * G_];
__device__ float         d_hbuf[2][B_ * 1024];
__device__ float         d_means[T_ * 32];
__device__ unsigned int  d_bar[2 * T_];
__device__ __nv_bfloat16 d_xhi[33554432];
__device__ __nv_bfloat16 d_xlo[33554432];
__device__ __nv_bfloat16 d_whi[3145728];
__device__ __nv_bfloat16 d_wlo[3145728];

// ================= helpers =================
__device__ __forceinline__ uint32_t smem_u32(const void* p) {
    uint32_t a;
    asm("{ .reg .u64 t; cvta.to.shared.u64 t, %1; cvt.u32.u64 %0, t; }" : "=r"(a) : "l"(p));
    return a;
}
__device__ __forceinline__ void ldsm_x4(uint32_t* r, uint32_t addr) {
    asm volatile("ldmatrix.sync.aligned.m8n8.x4.shared.b16 {%0,%1,%2,%3}, [%4];"
                 : "=r"(r[0]), "=r"(r[1]), "=r"(r[2]), "=r"(r[3]) : "r"(addr));
}
__device__ __forceinline__ void ldsm_x2(uint32_t* r, uint32_t addr) {
    asm volatile("ldmatrix.sync.aligned.m8n8.x2.shared.b16 {%0,%1}, [%2];"
                 : "=r"(r[0]), "=r"(r[1]) : "r"(addr));
}
__device__ __forceinline__ void mma_bf16(float* d, const uint32_t* a, const uint32_t* b) {
    asm volatile("mma.sync.aligned.m16n8k16.row.col.f32.bf16.bf16.f32 "
                 "{%0,%1,%2,%3}, {%4,%5,%6,%7}, {%8,%9}, {%0,%1,%2,%3};"
                 : "+f"(d[0]), "+f"(d[1]), "+f"(d[2]), "+f"(d[3])
                 : "r"(a[0]), "r"(a[1]), "r"(a[2]), "r"(a[3]), "r"(b[0]), "r"(b[1]));
}
#define CP_ASYNC(dst, src) \
    asm volatile("cp.async.ca.shared.global [%0], [%1], 16;" :: "r"(dst), "l"(src) : "memory")
#define CP_COMMIT() asm volatile("cp.async.commit_group;" ::: "memory")
#define CP_WAIT1()  asm volatile("cp.async.wait_group 1;" ::: "memory")
#define CP_WAIT0()  asm volatile("cp.async.wait_group 0;" ::: "memory")

__device__ __forceinline__ void split4(float4 v, uint2& hi, uint2& lo) {
    __nv_bfloat16 h0 = __float2bfloat16_rn(v.x), h1 = __float2bfloat16_rn(v.y);
    __nv_bfloat16 h2 = __float2bfloat16_rn(v.z), h3 = __float2bfloat16_rn(v.w);
    __nv_bfloat16 l0 = __float2bfloat16_rn(v.x - __bfloat162float(h0));
    __nv_bfloat16 l1 = __float2bfloat16_rn(v.y - __bfloat162float(h1));
    __nv_bfloat16 l2 = __float2bfloat16_rn(v.z - __bfloat162float(h2));
    __nv_bfloat16 l3 = __float2bfloat16_rn(v.w - __bfloat162float(h3));
    hi.x = (uint32_t)__bfloat16_as_ushort(h0) | ((uint32_t)__bfloat16_as_ushort(h1) << 16);
    hi.y = (uint32_t)__bfloat16_as_ushort(h2) | ((uint32_t)__bfloat16_as_ushort(h3) << 16);
    lo.x = (uint32_t)__bfloat16_as_ushort(l0) | ((uint32_t)__bfloat16_as_ushort(l1) << 16);
    lo.y = (uint32_t)__bfloat16_as_ushort(l2) | ((uint32_t)__bfloat16_as_ushort(l3) << 16);
}

// ---------------- init ----------------
__global__ void __launch_bounds__(256) init_kernel(const float* __restrict__ h0) {
    int idx = blockIdx.x * blockDim.x + threadIdx.x;
    if (idx < 2 * T_)   d_bar[idx]   = 0u;
    if (idx < T_ * 32)  d_means[idx] = 0.f;
    if (idx < B_ * 1024) d_hbuf[0][idx] = h0[idx];
}

// ---------------- fp32 -> bf16 hi/lo split ----------------
__global__ void __launch_bounds__(256) split_kernel(const float* __restrict__ src,
                                                    __nv_bfloat16* __restrict__ hi,
                                                    __nv_bfloat16* __restrict__ lo, int n4) {
    int i = blockIdx.x * blockDim.x + threadIdx.x;
    if (i >= n4) return;
    float4 v = ((const float4*)src)[i];
    uint2 h, l;
    split4(v, h, l);
    ((uint2*)hi)[i] = h;
    ((uint2*)lo)[i] = l;
}

// ---------------- Phase A: bf16 mma.sync GEMM, 2-way split ----------------
// C[32768,3072] = X @ W^T. 128x128 tile, 8 warps (2x4), warp tile 64x32, K-chunk 32.
#define ASTR        80                       // bytes per smem row (32 bf16 + 16B pad)
#define TILE_BYTES  (128 * ASTR)             // 10240
#define STAGE_BYTES (4 * TILE_BYTES)         // 40960: Xhi | Xlo | Whi | Wlo
#define SMEM_GEMM   (2 * STAGE_BYTES)        // 81920

__global__ void __launch_bounds__(256, 1) gemm_mma() {
    extern __shared__ __align__(16) char sm[];
    uint32_t sb = smem_u32(sm);
    const int tid = threadIdx.x, wid = tid >> 5, lane = tid & 31;
    const int m0 = blockIdx.y * 128, n0 = blockIdx.x * 128;
    const int wm = wid >> 2, wn = wid & 3;

    auto load_stage = [&](int c, int st) {
        uint32_t dst0 = sb + st * STAGE_BYTES;
        int kofs = c * 32;
#pragma unroll
        for (int t = 0; t < 8; t++) {
            int tile = t >> 1;
            int row  = ((t & 1) << 6) + (tid >> 2);
            int seg  = tid & 3;
            uint32_t dst = dst0 + tile * TILE_BYTES + row * ASTR + seg * 16;
            const __nv_bfloat16* src;
            if      (tile == 0) src = d_xhi + (size_t)(m0 + row) * 1024 + kofs + seg * 8;
            else if (tile == 1) src = d_xlo + (size_t)(m0 + row) * 1024 + kofs + seg * 8;
            else if (tile == 2) src = d_whi + (size_t)(n0 + row) * 1024 + kofs + seg * 8;
            else                src = d_wlo + (size_t)(n0 + row) * 1024 + kofs + seg * 8;
            CP_ASYNC(dst, (uint64_t)__cvta_generic_to_global(src));
        }
    };

    float acc[4][4][4];
#pragma unroll
    for (int i = 0; i < 4; i++)
#pragma unroll
        for (int j = 0; j < 4; j++)
#pragma unroll
            for (int k = 0; k < 4; k++) acc[i][j][k] = 0.f;

    load_stage(0, 0);
    CP_COMMIT();

    for (int c = 0; c < 32; c++) {
        int b = c & 1;
        if (c < 31) { load_stage(c + 1, b ^ 1); CP_COMMIT(); CP_WAIT1(); }
        else        { CP_WAIT0(); }
        __syncthreads();

        uint32_t base = sb + b * STAGE_BYTES;
#pragma unroll
        for (int s = 0; s < 2; s++) {
            uint32_t ah[4][4], al[4][4], bh[4][2], bl[4][2];
            uint32_t ak = s * 32 + ((lane >> 4) << 4);
#pragma unroll
            for (int mi = 0; mi < 4; mi++) {
                uint32_t ra = base + (wm * 64 + mi * 16 + (lane & 15)) * ASTR + ak;
                ldsm_x4(ah[mi], ra);
                ldsm_x4(al[mi], ra + TILE_BYTES);
            }
            uint32_t bk = s * 32 + (((lane >> 3) & 1) << 4);
#pragma unroll
            for (int ni = 0; ni < 4; ni++) {
                uint32_t rb = base + 2 * TILE_BYTES + (wn * 32 + ni * 8 + (lane & 7)) * ASTR + bk;
                ldsm_x2(bh[ni], rb);
                ldsm_x2(bl[ni], rb + TILE_BYTES);
            }
#pragma unroll
            for (int mi = 0; mi < 4; mi++)
#pragma unroll
                for (int ni = 0; ni < 4; ni++) {
                    mma_bf16(acc[mi][ni], ah[mi], bh[ni]);
                    mma_bf16(acc[mi][ni], ah[mi], bl[ni]);
                    mma_bf16(acc[mi][ni], al[mi], bh[ni]);
                }
        }
        __syncthreads();
    }

    // epilogue: direct fp32 stores (float2 per fragment row)
    int g = lane >> 2, q = lane & 3;
#pragma unroll
    for (int mi = 0; mi < 4; mi++) {
        int r0 = m0 + wm * 64 + mi * 16 + g;
#pragma unroll
        for (int ni = 0; ni < 4; ni++) {
            int cc = n0 + wn * 32 + ni * 8 + q * 2;
            *(float2*)(d_proj + (size_t)r0 * 3072 + cc)       = make_float2(acc[mi][ni][0], acc[mi][ni][1]);
            *(float2*)(d_proj + (size_t)(r0 + 8) * 3072 + cc) = make_float2(acc[mi][ni][2], acc[mi][ni][3]);
        }
    }
}

// ---------------- block reduce helper ----------------
__device__ __forceinline__ float2 block_reduce2(float s, float s2, float* sm) {
#pragma unroll
    for (int o = 16; o; o >>= 1) {
        s  += __shfl_down_sync(0xffffffffu, s,  o);
        s2 += __shfl_down_sync(0xffffffffu, s2, o);
    }
    int w = threadIdx.x >> 5, l = threadIdx.x & 31;
    if (l == 0) { sm[w] = s; sm[8 + w] = s2; }
    __syncthreads();
    if (threadIdx.x < 32) {
        s  = (l < 8) ? sm[l]     : 0.f;
        s2 = (l < 8) ? sm[8 + l] : 0.f;
#pragma unroll
        for (int o = 4; o; o >>= 1) {
            s  += __shfl_down_sync(0xffffffffu, s,  o);
            s2 += __shfl_down_sync(0xffffffffu, s2, o);
        }
        if (l == 0) { sm[16] = s; sm[17] = s2; }
    }
    __syncthreads();
    return make_float2(sm[16], sm[17]);
}

// ---------------- Phase B: LN_x in place ----------------
__global__ void __launch_bounds__(256) ln_x_kernel(const float* __restrict__ gamma,
                                                   const float* __restrict__ beta) {
    __shared__ float sm[18];
    float* row = d_proj + (size_t)blockIdx.x * 3072;
    const int tid = threadIdx.x;

    float v[8];
    float s = 0.f, s2 = 0.f;
#pragma unroll
    for (int i = 0; i < 8; i++) {
        float x = row[tid + (i << 8)];
        v[i] = x; s += x; s2 += x * x;
    }
    float2 r = block_reduce2(s, s2, sm);
    {
        float mean = r.x * (1.f / 2048.f);
        float var  = (r.y - 2048.f * mean * mean) * (1.f / 2047.f);
        float rstd = rsqrtf(var);
#pragma unroll
        for (int i = 0; i < 8; i++) {
            int c = tid + (i << 8);
            row[c] = gamma[c] * (v[i] - mean) * rstd + beta[c];
        }
    }
    __syncthreads();

    float vn[4];
    s = 0.f; s2 = 0.f;
#pragma unroll
    for (int i = 0; i < 4; i++) {
        float x = row[2048 + tid + (i << 8)];
        vn[i] = x; s += x; s2 += x * x;
    }
    r = block_reduce2(s, s2, sm);
    {
        float mean = r.x * (1.f / 1024.f);
        float var  = (r.y - 1024.f * mean * mean) * (1.f / 1023.f);
        float rstd = rsqrtf(var);
#pragma unroll
        for (int i = 0; i < 4; i++) {
            int c = 2048 + tid + (i << 8);
            row[c] = gamma[c] * (vn[i] - mean) * rstd + beta[c];
        }
    }
}

// ---------------- grid barrier ----------------
__device__ __forceinline__ void grid_barrier(int k) {
    __syncthreads();
    if (threadIdx.x == 0) {
        __threadfence();
        unsigned arrived = atomicAdd(&d_bar[k], 1u) + 1u;
        if (arrived < NCTA) {
            volatile unsigned* p = &d_bar[k];
            while (*p < NCTA) { __nanosleep(32); }
        }
    }
    __syncthreads();
}

// ---------------- Phase C: persistent recurrent kernel (HMMA inner GEMM) ----------------
#define WSB      2064                 // bytes per bf16 row (1024 bf16 + 8 pad)
#define OFF_WHI  0
#define OFF_WLO  49536
#define OFF_HHI  99072
#define OFF_HLO  132096
#define OFF_RED  165120
#define OFF_SSUM 177408
#define SMEM_REC 177536

__global__ void __launch_bounds__(256, 1) gru_rec(const float* __restrict__ w_hh,
                                                  const float* __restrict__ b_hh,
                                                  const float* __restrict__ gamma_hh,
                                                  float* __restrict__ out) {
    extern __shared__ __align__(16) char sm[];
    uint32_t sb = smem_u32(sm);
    float* red  = (float*)(sm + OFF_RED);
    float* ssum = (float*)(sm + OFF_SSUM);

    const int cta  = blockIdx.x;
    const int tid  = threadIdx.x;
    const int c0   = cta * COLS;
    const int warp = tid >> 5, lane = tid & 31;

    // stage w_hh slice (24 x 1024) into smem as bf16 hi/lo, once
    for (int i = tid; i < COLS * 256; i += 256) {
        int c  = i >> 8;
        int kq = (i & 255) << 2;
        float4 v = *(const float4*)(w_hh + (size_t)(c0 + c) * 1024 + kq);
        uint2 hi, lo;
        split4(v, hi, lo);
        *(uint2*)(sm + OFF_WHI + c * WSB + kq * 2) = hi;
        *(uint2*)(sm + OFF_WLO + c * WSB + kq * 2) = lo;
    }

    const uint32_t ha_base = sb + OFF_HHI + (lane & 15) * WSB + warp * 256 + ((lane >> 4) << 4);
    const uint32_t wb_base = sb + OFF_WHI + (lane & 7) * WSB  + warp * 256 + (((lane >> 3) & 1) << 4);
    const int g = lane >> 2, q = lane & 3;

    for (int t = 0; t < T_; t++) {
        const float* hb = d_hbuf[t & 1];
        // stage h (16 x 1024) fp32 -> bf16 hi/lo smem
        for (int i = tid; i < 4096; i += 256) {
            int b  = i >> 8;
            int kq = (i & 255) << 2;
            float4 v = __ldcg((const float4*)(hb + b * 1024 + kq));
            uint2 hi, lo;
            split4(v, hi, lo);
            *(uint2*)(sm + OFF_HHI + b * WSB + kq * 2) = hi;
            *(uint2*)(sm + OFF_HLO + b * WSB + kq * 2) = lo;
        }
        if (tid < 32) ssum[tid] = 0.f;
        __syncthreads();

        // warp k-split HMMA: each warp handles k in [warp*128, warp*128+128)
        float acc[3][4];
#pragma unroll
        for (int ni = 0; ni < 3; ni++)
#pragma unroll
            for (int j = 0; j < 4; j++) acc[ni][j] = 0.f;

#pragma unroll
        for (int s = 0; s < 8; s++) {
            uint32_t ah[4], al[4];
            ldsm_x4(ah, ha_base + s * 32);
            ldsm_x4(al, ha_base + s * 32 + (OFF_HLO - OFF_HHI));
#pragma unroll
            for (int ni = 0; ni < 3; ni++) {
                uint32_t wb = wb_base + ni * 8 * WSB + s * 32;
                uint32_t bhf[2], blf[2];
                ldsm_x2(bhf, wb);
                ldsm_x2(blf, wb + (OFF_WLO - OFF_WHI));
                mma_bf16(acc[ni], ah, bhf);
                mma_bf16(acc[ni], ah, blf);
                mma_bf16(acc[ni], al, bhf);
            }
        }
        // store partials: red[warp][batch*24 + col]
        float* rp = red + warp * 384;
#pragma unroll
        for (int ni = 0; ni < 3; ni++) {
            int col = ni * 8 + q * 2;
            rp[g * 24 + col]           = acc[ni][0];
            rp[g * 24 + col + 1]       = acc[ni][1];
            rp[(g + 8) * 24 + col]     = acc[ni][2];
            rp[(g + 8) * 24 + col + 1] = acc[ni][3];
        }
        __syncthreads();

        // cross-warp reduce, write hh, accumulate per-(grp,b) column sums
        for (int o = tid; o < 384; o += 256) {
            float s = 0.f;
#pragma unroll
            for (int w = 0; w < 8; w++) s += red[w * 384 + o];
            int b  = o / 24;
            int c  = o - b * 24;
            int gc = c0 + c;
            d_hh[b * G_ + gc] = s;
            atomicAdd(&ssum[((gc >= 2048) ? 16 : 0) + b], s);
        }
        __syncthreads();
        if (tid < 32) atomicAdd(&d_means[t * 32 + tid], ssum[tid]);

        grid_barrier(2 * t);

        // gate + state update
        if (tid < 128) {
            int b = cta >> 3;
            int j = ((cta & 7) << 7) + tid;
            float mrz = __ldcg(&d_means[t * 32 + b])      * (1.f / 2048.f);
            float mn  = __ldcg(&d_means[t * 32 + 16 + b]) * (1.f / 1024.f);
            float hr  = __ldcg(&d_hh[b * G_ + j]);
            float hz  = __ldcg(&d_hh[b * G_ + 1024 + j]);
            float hn  = __ldcg(&d_hh[b * G_ + 2048 + j]);
            float lnr = gamma_hh[j]        * (hr - mrz) + b_hh[j];
            float lnz = gamma_hh[1024 + j] * (hz - mrz) + b_hh[1024 + j];
            float lnn = gamma_hh[2048 + j] * (hn - mn)  + b_hh[2048 + j];
            size_t bt = (size_t)b * T_ + t;
            const float* xr = d_proj + bt * 3072;
            float rg   = 1.f / (1.f + expf(-(xr[j] + lnr)));
            float zg   = 1.f / (1.f + expf(-(xr[1024 + j] + lnz)));
            float ng   = tanhf(xr[2048 + j] + rg * lnn);
            float hold = __ldcg(&hb[b * 1024 + j]);
            float hnew = (1.f - zg) * ng + zg * hold;
            d_hbuf[(t + 1) & 1][b * 1024 + j] = hnew;
            out[bt * 1024 + j] = hnew;
            if (t == T_ - 1) out[(size_t)B_ * T_ * 1024 + b * 1024 + j] = hnew;
        }
        grid_barrier(2 * t + 1);
    }
}

// ---------------- launch ----------------
extern "C" void kernel_launch(void* const* d_in, const int* in_sizes, int n_in,
                              void* d_out, int out_size) {
    const float* xs   = (const float*)d_in[0];
    const float* h0   = (const float*)d_in[1];
    const float* w_ih = (const float*)d_in[2];
    const float* w_hh = (const float*)d_in[3];
    const float* b_ih = (const float*)d_in[4];
    const float* b_hh = (const float*)d_in[5];
    const float* g_ih = (const float*)d_in[6];
    const float* g_hh = (const float*)d_in[7];
    float* out = (float*)d_out;

    cudaFuncSetAttribute(gru_rec,  cudaFuncAttributeMaxDynamicSharedMemorySize, SMEM_REC);
    cudaFuncSetAttribute(gemm_mma, cudaFuncAttributeMaxDynamicSharedMemorySize, SMEM_GEMM);

    init_kernel<<<256, 256>>>(h0);

    __nv_bfloat16 *xhi_p, *xlo_p, *whi_p, *wlo_p;
    cudaGetSymbolAddress((void**)&xhi_p, d_xhi);
    cudaGetSymbolAddress((void**)&xlo_p, d_xlo);
    cudaGetSymbolAddress((void**)&whi_p, d_whi);
    cudaGetSymbolAddress((void**)&wlo_p, d_wlo);
    split_kernel<<<(33554432 / 4 + 255) / 256, 256>>>(xs, xhi_p, xlo_p, 33554432 / 4);
    split_kernel<<<(3145728 / 4 + 255) / 256, 256>>>(w_ih, whi_p, wlo_p, 3145728 / 4);

    dim3 g(G_ / 128, 32768 / 128);   // (24, 256)
    gemm_mma<<<g, 256, SMEM_GEMM>>>();

    ln_x_kernel<<<16 * 2048, 256>>>(g_ih, b_ih);
    gru_rec<<<NCTA, 256, SMEM_REC>>>(w_hh, b_hh, g_hh, out);
}

// round 4
// speedup vs baseline: 2.6467x; 2.1034x over previous
#include <cuda_runtime.h>
#include <cuda_bf16.h>
#include <cstdint>

#define B_   16
#define T_   2048
#define G_   3072
#define NCTA 128

// ---------------- scratch (static device memory; no allocation) ----------------
__device__ float         d_proj[100663296ULL];   // 32768 x 3072 fp32
__device__ float         d_wsum[2048];           // [rz(1024) | n(1024)] column sums of w_hh
__device__ unsigned int  d_bar[2 * T_];
__device__ __nv_bfloat16 d_hsp[2][2][B_ * 1024]; // [buf][hi/lo] hidden state, bf16 split
__device__ __nv_bfloat16 d_xhi[33554432];
__device__ __nv_bfloat16 d_xlo[33554432];
__device__ __nv_bfloat16 d_whi[3145728];
__device__ __nv_bfloat16 d_wlo[3145728];

// ================= helpers =================
__device__ __forceinline__ uint32_t smem_u32(const void* p) {
    uint32_t a;
    asm("{ .reg .u64 t; cvta.to.shared.u64 t, %1; cvt.u32.u64 %0, t; }" : "=r"(a) : "l"(p));
    return a;
}
__device__ __forceinline__ void ldsm_x4(uint32_t* r, uint32_t addr) {
    asm volatile("ldmatrix.sync.aligned.m8n8.x4.shared.b16 {%0,%1,%2,%3}, [%4];"
                 : "=r"(r[0]), "=r"(r[1]), "=r"(r[2]), "=r"(r[3]) : "r"(addr));
}
__device__ __forceinline__ void ldsm_x2(uint32_t* r, uint32_t addr) {
    asm volatile("ldmatrix.sync.aligned.m8n8.x2.shared.b16 {%0,%1}, [%2];"
                 : "=r"(r[0]), "=r"(r[1]) : "r"(addr));
}
__device__ __forceinline__ void mma_bf16(float* d, const uint32_t* a, const uint32_t* b) {
    asm volatile("mma.sync.aligned.m16n8k16.row.col.f32.bf16.bf16.f32 "
                 "{%0,%1,%2,%3}, {%4,%5,%6,%7}, {%8,%9}, {%0,%1,%2,%3};"
                 : "+f"(d[0]), "+f"(d[1]), "+f"(d[2]), "+f"(d[3])
                 : "r"(a[0]), "r"(a[1]), "r"(a[2]), "r"(a[3]), "r"(b[0]), "r"(b[1]));
}
#define CP_ASYNC(dst, src) \
    asm volatile("cp.async.ca.shared.global [%0], [%1], 16;" :: "r"(dst), "l"(src) : "memory")
#define CP_COMMIT() asm volatile("cp.async.commit_group;" ::: "memory")
#define CP_WAIT1()  asm volatile("cp.async.wait_group 1;" ::: "memory")
#define CP_WAIT0()  asm volatile("cp.async.wait_group 0;" ::: "memory")

__device__ __forceinline__ void split4(float4 v, uint2& hi, uint2& lo) {
    __nv_bfloat16 h0 = __float2bfloat16_rn(v.x), h1 = __float2bfloat16_rn(v.y);
    __nv_bfloat16 h2 = __float2bfloat16_rn(v.z), h3 = __float2bfloat16_rn(v.w);
    __nv_bfloat16 l0 = __float2bfloat16_rn(v.x - __bfloat162float(h0));
    __nv_bfloat16 l1 = __float2bfloat16_rn(v.y - __bfloat162float(h1));
    __nv_bfloat16 l2 = __float2bfloat16_rn(v.z - __bfloat162float(h2));
    __nv_bfloat16 l3 = __float2bfloat16_rn(v.w - __bfloat162float(h3));
    hi.x = (uint32_t)__bfloat16_as_ushort(h0) | ((uint32_t)__bfloat16_as_ushort(h1) << 16);
    hi.y = (uint32_t)__bfloat16_as_ushort(h2) | ((uint32_t)__bfloat16_as_ushort(h3) << 16);
    lo.x = (uint32_t)__bfloat16_as_ushort(l0) | ((uint32_t)__bfloat16_as_ushort(l1) << 16);
    lo.y = (uint32_t)__bfloat16_as_ushort(l2) | ((uint32_t)__bfloat16_as_ushort(l3) << 16);
}

// ---------------- init: zero barriers + wsum, split h0 ----------------
__global__ void __launch_bounds__(256) init_kernel(const float* __restrict__ h0) {
    int idx = blockIdx.x * blockDim.x + threadIdx.x;
    if (idx < 2 * T_)  d_bar[idx]  = 0u;
    if (idx < 2048)    d_wsum[idx] = 0.f;
    if (idx < B_ * 1024) {
        float v = h0[idx];
        __nv_bfloat16 hi = __float2bfloat16_rn(v);
        __nv_bfloat16 lo = __float2bfloat16_rn(v - __bfloat162float(hi));
        d_hsp[0][0][idx] = hi;
        d_hsp[0][1][idx] = lo;
    }
}

// ---------------- wsum: column sums of w_hh (rz rows / n rows) ----------------
__global__ void __launch_bounds__(256) wsum_kernel(const float* __restrict__ w_hh) {
    int k  = blockIdx.x * 256 + threadIdx.x;
    int j0 = blockIdx.y * 256;
    float s = 0.f;
#pragma unroll 4
    for (int j = 0; j < 256; j++) s += w_hh[(size_t)(j0 + j) * 1024 + k];
    atomicAdd(&d_wsum[(j0 >= 2048 ? 1024 : 0) + k], s);
}

// ---------------- fp32 -> bf16 hi/lo split ----------------
__global__ void __launch_bounds__(256) split_kernel(const float* __restrict__ src,
                                                    __nv_bfloat16* __restrict__ hi,
                                                    __nv_bfloat16* __restrict__ lo, int n4) {
    int i = blockIdx.x * blockDim.x + threadIdx.x;
    if (i >= n4) return;
    float4 v = ((const float4*)src)[i];
    uint2 h, l;
    split4(v, h, l);
    ((uint2*)hi)[i] = h;
    ((uint2*)lo)[i] = l;
}

// ---------------- Phase A: bf16 mma.sync GEMM, 2-way split (unchanged) ----------------
#define ASTR        80
#define TILE_BYTES  (128 * ASTR)
#define STAGE_BYTES (4 * TILE_BYTES)
#define SMEM_GEMM   (2 * STAGE_BYTES)

__global__ void __launch_bounds__(256, 1) gemm_mma() {
    extern __shared__ __align__(16) char sm[];
    uint32_t sb = smem_u32(sm);
    const int tid = threadIdx.x, wid = tid >> 5, lane = tid & 31;
    const int m0 = blockIdx.y * 128, n0 = blockIdx.x * 128;
    const int wm = wid >> 2, wn = wid & 3;

    auto load_stage = [&](int c, int st) {
        uint32_t dst0 = sb + st * STAGE_BYTES;
        int kofs = c * 32;
#pragma unroll
        for (int t = 0; t < 8; t++) {
            int tile = t >> 1;
            int row  = ((t & 1) << 6) + (tid >> 2);
            int seg  = tid & 3;
            uint32_t dst = dst0 + tile * TILE_BYTES + row * ASTR + seg * 16;
            const __nv_bfloat16* src;
            if      (tile == 0) src = d_xhi + (size_t)(m0 + row) * 1024 + kofs + seg * 8;
            else if (tile == 1) src = d_xlo + (size_t)(m0 + row) * 1024 + kofs + seg * 8;
            else if (tile == 2) src = d_whi + (size_t)(n0 + row) * 1024 + kofs + seg * 8;
            else                src = d_wlo + (size_t)(n0 + row) * 1024 + kofs + seg * 8;
            CP_ASYNC(dst, (uint64_t)__cvta_generic_to_global(src));
        }
    };

    float acc[4][4][4];
#pragma unroll
    for (int i = 0; i < 4; i++)
#pragma unroll
        for (int j = 0; j < 4; j++)
#pragma unroll
            for (int k = 0; k < 4; k++) acc[i][j][k] = 0.f;

    load_stage(0, 0);
    CP_COMMIT();

    for (int c = 0; c < 32; c++) {
        int b = c & 1;
        if (c < 31) { load_stage(c + 1, b ^ 1); CP_COMMIT(); CP_WAIT1(); }
        else        { CP_WAIT0(); }
        __syncthreads();

        uint32_t base = sb + b * STAGE_BYTES;
#pragma unroll
        for (int s = 0; s < 2; s++) {
            uint32_t ah[4][4], al[4][4], bh[4][2], bl[4][2];
            uint32_t ak = s * 32 + ((lane >> 4) << 4);
#pragma unroll
            for (int mi = 0; mi < 4; mi++) {
                uint32_t ra = base + (wm * 64 + mi * 16 + (lane & 15)) * ASTR + ak;
                ldsm_x4(ah[mi], ra);
                ldsm_x4(al[mi], ra + TILE_BYTES);
            }
            uint32_t bk = s * 32 + (((lane >> 3) & 1) << 4);
#pragma unroll
            for (int ni = 0; ni < 4; ni++) {
                uint32_t rb = base + 2 * TILE_BYTES + (wn * 32 + ni * 8 + (lane & 7)) * ASTR + bk;
                ldsm_x2(bh[ni], rb);
                ldsm_x2(bl[ni], rb + TILE_BYTES);
            }
#pragma unroll
            for (int mi = 0; mi < 4; mi++)
#pragma unroll
                for (int ni = 0; ni < 4; ni++) {
                    mma_bf16(acc[mi][ni], ah[mi], bh[ni]);
                    mma_bf16(acc[mi][ni], ah[mi], bl[ni]);
                    mma_bf16(acc[mi][ni], al[mi], bh[ni]);
                }
        }
        __syncthreads();
    }

    int g = lane >> 2, q = lane & 3;
#pragma unroll
    for (int mi = 0; mi < 4; mi++) {
        int r0 = m0 + wm * 64 + mi * 16 + g;
#pragma unroll
        for (int ni = 0; ni < 4; ni++) {
            int cc = n0 + wn * 32 + ni * 8 + q * 2;
            *(float2*)(d_proj + (size_t)r0 * 3072 + cc)       = make_float2(acc[mi][ni][0], acc[mi][ni][1]);
            *(float2*)(d_proj + (size_t)(r0 + 8) * 3072 + cc) = make_float2(acc[mi][ni][2], acc[mi][ni][3]);
        }
    }
}

// ---------------- block reduce helper ----------------
__device__ __forceinline__ float2 block_reduce2(float s, float s2, float* sm) {
#pragma unroll
    for (int o = 16; o; o >>= 1) {
        s  += __shfl_down_sync(0xffffffffu, s,  o);
        s2 += __shfl_down_sync(0xffffffffu, s2, o);
    }
    int w = threadIdx.x >> 5, l = threadIdx.x & 31;
    if (l == 0) { sm[w] = s; sm[8 + w] = s2; }
    __syncthreads();
    if (threadIdx.x < 32) {
        s  = (l < 8) ? sm[l]     : 0.f;
        s2 = (l < 8) ? sm[8 + l] : 0.f;
#pragma unroll
        for (int o = 4; o; o >>= 1) {
            s  += __shfl_down_sync(0xffffffffu, s,  o);
            s2 += __shfl_down_sync(0xffffffffu, s2, o);
        }
        if (l == 0) { sm[16] = s; sm[17] = s2; }
    }
    __syncthreads();
    return make_float2(sm[16], sm[17]);
}

// ---------------- Phase B: LN_x in place ----------------
__global__ void __launch_bounds__(256) ln_x_kernel(const float* __restrict__ gamma,
                                                   const float* __restrict__ beta) {
    __shared__ float sm[18];
    float* row = d_proj + (size_t)blockIdx.x * 3072;
    const int tid = threadIdx.x;

    float v[8];
    float s = 0.f, s2 = 0.f;
#pragma unroll
    for (int i = 0; i < 8; i++) {
        float x = row[tid + (i << 8)];
        v[i] = x; s += x; s2 += x * x;
    }
    float2 r = block_reduce2(s, s2, sm);
    {
        float mean = r.x * (1.f / 2048.f);
        float var  = (r.y - 2048.f * mean * mean) * (1.f / 2047.f);
        float rstd = rsqrtf(var);
#pragma unroll
        for (int i = 0; i < 8; i++) {
            int c = tid + (i << 8);
            row[c] = gamma[c] * (v[i] - mean) * rstd + beta[c];
        }
    }
    __syncthreads();

    float vn[4];
    s = 0.f; s2 = 0.f;
#pragma unroll
    for (int i = 0; i < 4; i++) {
        float x = row[2048 + tid + (i << 8)];
        vn[i] = x; s += x; s2 += x * x;
    }
    r = block_reduce2(s, s2, sm);
    {
        float mean = r.x * (1.f / 1024.f);
        float var  = (r.y - 1024.f * mean * mean) * (1.f / 1023.f);
        float rstd = rsqrtf(var);
#pragma unroll
        for (int i = 0; i < 4; i++) {
            int c = 2048 + tid + (i << 8);
            row[c] = gamma[c] * (vn[i] - mean) * rstd + beta[c];
        }
    }
}

// ---------------- grid barrier ----------------
__device__ __forceinline__ void grid_barrier(int k) {
    __syncthreads();
    if (threadIdx.x == 0) {
        __threadfence();
        unsigned arrived = atomicAdd(&d_bar[k], 1u) + 1u;
        if (arrived < NCTA) {
            volatile unsigned* p = &d_bar[k];
            while (*p < NCTA) { __nanosleep(32); }
        }
    }
    __syncthreads();
}

// ---------------- Phase C: persistent recurrent kernel, fully local update ----------------
// CTA i owns output columns j = i*8 .. i*8+7 across all three gates.
// B tile (32 rows): [0..7]=w_r rows, [8..15]=w_z, [16..23]=w_n, 24=wsum_rz, 25=wsum_n, 26..31=0.
#define WSB      2064
#define OFF_WHI  0
#define OFF_WLO  66048
#define OFF_HHI  132096
#define OFF_HLO  165120
#define OFF_RED  198144      // 8 warps x 512 floats
#define OFF_FIN  214528      // 512 floats
#define SMEM_REC 216576

__global__ void __launch_bounds__(256, 1) gru_rec(const float* __restrict__ w_hh,
                                                  const float* __restrict__ b_hh,
                                                  const float* __restrict__ gamma_hh,
                                                  const float* __restrict__ h0,
                                                  float* __restrict__ out) {
    extern __shared__ __align__(16) char sm[];
    uint32_t sb = smem_u32(sm);
    float* red = (float*)(sm + OFF_RED);
    float* fin = (float*)(sm + OFF_FIN);

    const int cta  = blockIdx.x;
    const int tid  = threadIdx.x;
    const int j0   = cta * 8;
    const int warp = tid >> 5, lane = tid & 31;

    // --- startup: stage own w rows (24) + wsum rows (2) as bf16 hi/lo; zero rows 26..31 ---
    for (int i = tid; i < 24 * 256; i += 256) {
        int c  = i >> 8;                       // B-tile row 0..23
        int kq = (i & 255) << 2;
        int src_row = (c >> 3) * 1024 + j0 + (c & 7);
        float4 v = *(const float4*)(w_hh + (size_t)src_row * 1024 + kq);
        uint2 hi, lo;
        split4(v, hi, lo);
        *(uint2*)(sm + OFF_WHI + c * WSB + kq * 2) = hi;
        *(uint2*)(sm + OFF_WLO + c * WSB + kq * 2) = lo;
    }
    for (int i = tid; i < 2 * 256; i += 256) {
        int c  = i >> 8;                       // 0: rz, 1: n
        int kq = (i & 255) << 2;
        float4 v = *(const float4*)(d_wsum + c * 1024 + kq);
        uint2 hi, lo;
        split4(v, hi, lo);
        *(uint2*)(sm + OFF_WHI + (24 + c) * WSB + kq * 2) = hi;
        *(uint2*)(sm + OFF_WLO + (24 + c) * WSB + kq * 2) = lo;
    }
    for (int i = tid; i < 6 * 129; i += 256) {
        int r = 26 + i / 129, seg = i % 129;
        *(uint4*)(sm + OFF_WHI + r * WSB + seg * 16) = make_uint4(0, 0, 0, 0);
        *(uint4*)(sm + OFF_WLO + r * WSB + seg * 16) = make_uint4(0, 0, 0, 0);
    }

    // per-thread constants for the update phase
    const int ub = tid >> 3, uj = tid & 7;     // batch, local col (tid < 128)
    const int jg = j0 + uj;
    float g_r = 0, g_z = 0, g_n = 0, bb_r = 0, bb_z = 0, bb_n = 0, h_prev = 0;
    if (tid < 128) {
        g_r  = gamma_hh[jg];        bb_r = b_hh[jg];
        g_z  = gamma_hh[1024 + jg]; bb_z = b_hh[1024 + jg];
        g_n  = gamma_hh[2048 + jg]; bb_n = b_hh[2048 + jg];
        h_prev = h0[ub * 1024 + jg];
    }
    __syncthreads();

    const uint32_t ha_base = sb + OFF_HHI + (lane & 15) * WSB + warp * 256 + ((lane >> 4) << 4);
    const uint32_t wb_base = sb + OFF_WHI + (lane & 7) * WSB  + warp * 256 + (((lane >> 3) & 1) << 4);
    const int g = lane >> 2, q = lane & 3;

    for (int t = 0; t < T_; t++) {
        // prefetch x row entries (independent of barrier-protected state)
        float x_r = 0.f, x_z = 0.f, x_n = 0.f;
        if (tid < 128) {
            const float* xr = d_proj + ((size_t)ub * T_ + t) * 3072;
            x_r = xr[jg]; x_z = xr[1024 + jg]; x_n = xr[2048 + jg];
        }

        // stage h bf16 hi/lo (pure copy, L1-bypass)
        const uint4* shi = (const uint4*)d_hsp[t & 1][0];
        const uint4* slo = (const uint4*)d_hsp[t & 1][1];
        for (int i = tid; i < 2048; i += 256) {
            int b   = i >> 7;
            int seg = i & 127;
            uint4 v = __ldcg(shi + i);
            *(uint4*)(sm + OFF_HHI + b * WSB + seg * 16) = v;
            uint4 w = __ldcg(slo + i);
            *(uint4*)(sm + OFF_HLO + b * WSB + seg * 16) = w;
        }
        __syncthreads();

        // warp k-split HMMA: 16(b) x 32(col) output, K range = warp*128..+128
        float acc[4][4];
#pragma unroll
        for (int ni = 0; ni < 4; ni++)
#pragma unroll
            for (int j = 0; j < 4; j++) acc[ni][j] = 0.f;

#pragma unroll
        for (int s = 0; s < 8; s++) {
            uint32_t ah[4], al[4];
            ldsm_x4(ah, ha_base + s * 32);
            ldsm_x4(al, ha_base + s * 32 + (OFF_HLO - OFF_HHI));
#pragma unroll
            for (int ni = 0; ni < 4; ni++) {
                uint32_t wb = wb_base + ni * 8 * WSB + s * 32;
                uint32_t bhf[2], blf[2];
                ldsm_x2(bhf, wb);
                ldsm_x2(blf, wb + (OFF_WLO - OFF_WHI));
                mma_bf16(acc[ni], ah, bhf);
                mma_bf16(acc[ni], ah, blf);
                mma_bf16(acc[ni], al, bhf);
            }
        }
        float* rp = red + warp * 512;
#pragma unroll
        for (int ni = 0; ni < 4; ni++) {
            int col = ni * 8 + q * 2;
            rp[g * 32 + col]            = acc[ni][0];
            rp[g * 32 + col + 1]        = acc[ni][1];
            rp[(g + 8) * 32 + col]      = acc[ni][2];
            rp[(g + 8) * 32 + col + 1]  = acc[ni][3];
        }
        __syncthreads();

        // cross-warp reduce into fin[b*32 + col]
        for (int o = tid; o < 512; o += 256) {
            float s = 0.f;
#pragma unroll
            for (int w = 0; w < 8; w++) s += red[w * 512 + o];
            fin[o] = s;
        }
        __syncthreads();

        // fully local gate + state update
        if (tid < 128) {
            const float* fb = fin + ub * 32;
            float mrz = fb[24] * (1.f / 2048.f);
            float mn  = fb[25] * (1.f / 1024.f);
            float lnr = g_r * (fb[uj]      - mrz) + bb_r;
            float lnz = g_z * (fb[8 + uj]  - mrz) + bb_z;
            float lnn = g_n * (fb[16 + uj] - mn)  + bb_n;
            float rg  = 1.f / (1.f + expf(-(x_r + lnr)));
            float zg  = 1.f / (1.f + expf(-(x_z + lnz)));
            float ng  = tanhf(x_n + rg * lnn);
            float hnew = (1.f - zg) * ng + zg * h_prev;
            h_prev = hnew;
            size_t bt = (size_t)ub * T_ + t;
            out[bt * 1024 + jg] = hnew;
            if (t == T_ - 1) out[(size_t)B_ * T_ * 1024 + ub * 1024 + jg] = hnew;
            __nv_bfloat16 hi = __float2bfloat16_rn(hnew);
            __nv_bfloat16 lo = __float2bfloat16_rn(hnew - __bfloat162float(hi));
            d_hsp[(t + 1) & 1][0][ub * 1024 + jg] = hi;
            d_hsp[(t + 1) & 1][1][ub * 1024 + jg] = lo;
        }
        grid_barrier(t);
    }
}

// ---------------- launch ----------------
extern "C" void kernel_launch(void* const* d_in, const int* in_sizes, int n_in,
                              void* d_out, int out_size) {
    const float* xs   = (const float*)d_in[0];
    const float* h0   = (const float*)d_in[1];
    const float* w_ih = (const float*)d_in[2];
    const float* w_hh = (const float*)d_in[3];
    const float* b_ih = (const float*)d_in[4];
    const float* b_hh = (const float*)d_in[5];
    const float* g_ih = (const float*)d_in[6];
    const float* g_hh = (const float*)d_in[7];
    float* out = (float*)d_out;

    cudaFuncSetAttribute(gru_rec,  cudaFuncAttributeMaxDynamicSharedMemorySize, SMEM_REC);
    cudaFuncSetAttribute(gemm_mma, cudaFuncAttributeMaxDynamicSharedMemorySize, SMEM_GEMM);

    init_kernel<<<256, 256>>>(h0);

    dim3 wg(4, 12);
    wsum_kernel<<<wg, 256>>>(w_hh);

    __nv_bfloat16 *xhi_p, *xlo_p, *whi_p, *wlo_p;
    cudaGetSymbolAddress((void**)&xhi_p, d_xhi);
    cudaGetSymbolAddress((void**)&xlo_p, d_xlo);
    cudaGetSymbolAddress((void**)&whi_p, d_whi);
    cudaGetSymbolAddress((void**)&wlo_p, d_wlo);
    split_kernel<<<(33554432 / 4 + 255) / 256, 256>>>(xs, xhi_p, xlo_p, 33554432 / 4);
    split_kernel<<<(3145728 / 4 + 255) / 256, 256>>>(w_ih, whi_p, wlo_p, 3145728 / 4);

    dim3 g(G_ / 128, 32768 / 128);
    gemm_mma<<<g, 256, SMEM_GEMM>>>();

    ln_x_kernel<<<16 * 2048, 256>>>(g_ih, b_ih);
    gru_rec<<<NCTA, 256, SMEM_REC>>>(w_hh, b_hh, g_hh, h0, out);
}

// round 5
// speedup vs baseline: 3.0651x; 1.1581x over previous
#include <cuda_runtime.h>
#include <cuda_bf16.h>
#include <cstdint>

#define B_   16
#define T_   2048
#define G_   3072
#define NCTA 128

// ---------------- scratch (static device memory; no allocation) ----------------
__device__ float         d_proj[100663296ULL];   // 32768 x 3072 fp32
__device__ float         d_wsum[2048];           // [rz | n] column sums of w_hh
__device__ unsigned int  d_bar[2 * T_];
// hidden state in m16n8k16 A-fragment order: [buf][hi/lo][ (kg*32+lane)*4+reg ][halfword]
__device__ __align__(16) unsigned short d_hfrag[2][2][32768];
__device__ __nv_bfloat16 d_xhi[33554432];
__device__ __nv_bfloat16 d_xlo[33554432];
__device__ __nv_bfloat16 d_whi[3145728];
__device__ __nv_bfloat16 d_wlo[3145728];

// ================= helpers =================
__device__ __forceinline__ uint32_t smem_u32(const void* p) {
    uint32_t a;
    asm("{ .reg .u64 t; cvta.to.shared.u64 t, %1; cvt.u32.u64 %0, t; }" : "=r"(a) : "l"(p));
    return a;
}
__device__ __forceinline__ void ldsm_x4(uint32_t* r, uint32_t addr) {
    asm volatile("ldmatrix.sync.aligned.m8n8.x4.shared.b16 {%0,%1,%2,%3}, [%4];"
                 : "=r"(r[0]), "=r"(r[1]), "=r"(r[2]), "=r"(r[3]) : "r"(addr));
}
__device__ __forceinline__ void ldsm_x2(uint32_t* r, uint32_t addr) {
    asm volatile("ldmatrix.sync.aligned.m8n8.x2.shared.b16 {%0,%1}, [%2];"
                 : "=r"(r[0]), "=r"(r[1]) : "r"(addr));
}
__device__ __forceinline__ void mma_bf16(float* d, const uint32_t* a, const uint32_t* b) {
    asm volatile("mma.sync.aligned.m16n8k16.row.col.f32.bf16.bf16.f32 "
                 "{%0,%1,%2,%3}, {%4,%5,%6,%7}, {%8,%9}, {%0,%1,%2,%3};"
                 : "+f"(d[0]), "+f"(d[1]), "+f"(d[2]), "+f"(d[3])
                 : "r"(a[0]), "r"(a[1]), "r"(a[2]), "r"(a[3]), "r"(b[0]), "r"(b[1]));
}
#define CP_ASYNC(dst, src) \
    asm volatile("cp.async.ca.shared.global [%0], [%1], 16;" :: "r"(dst), "l"(src) : "memory")
#define CP_COMMIT() asm volatile("cp.async.commit_group;" ::: "memory")
#define CP_WAIT1()  asm volatile("cp.async.wait_group 1;" ::: "memory")
#define CP_WAIT0()  asm volatile("cp.async.wait_group 0;" ::: "memory")

__device__ __forceinline__ void split4(float4 v, uint2& hi, uint2& lo) {
    __nv_bfloat16 h0 = __float2bfloat16_rn(v.x), h1 = __float2bfloat16_rn(v.y);
    __nv_bfloat16 h2 = __float2bfloat16_rn(v.z), h3 = __float2bfloat16_rn(v.w);
    __nv_bfloat16 l0 = __float2bfloat16_rn(v.x - __bfloat162float(h0));
    __nv_bfloat16 l1 = __float2bfloat16_rn(v.y - __bfloat162float(h1));
    __nv_bfloat16 l2 = __float2bfloat16_rn(v.z - __bfloat162float(h2));
    __nv_bfloat16 l3 = __float2bfloat16_rn(v.w - __bfloat162float(h3));
    hi.x = (uint32_t)__bfloat16_as_ushort(h0) | ((uint32_t)__bfloat16_as_ushort(h1) << 16);
    hi.y = (uint32_t)__bfloat16_as_ushort(h2) | ((uint32_t)__bfloat16_as_ushort(h3) << 16);
    lo.x = (uint32_t)__bfloat16_as_ushort(l0) | ((uint32_t)__bfloat16_as_ushort(l1) << 16);
    lo.y = (uint32_t)__bfloat16_as_ushort(l2) | ((uint32_t)__bfloat16_as_ushort(l3) << 16);
}

// A-fragment u16 index for h element (b, hcol)
__device__ __forceinline__ int hfrag_idx(int b, int hcol) {
    int kg    = hcol >> 4;
    int col16 = hcol & 15;
    int lane  = (b & 7) * 4 + ((col16 >> 1) & 3);
    int reg   = ((col16 >> 3) << 1) | (b >> 3);
    return (((kg * 32 + lane) << 2) + reg) * 2 + (col16 & 1);
}

// ---------------- init: zero barriers + wsum, write h0 into fragment layout ----------------
__global__ void __launch_bounds__(256) init_kernel(const float* __restrict__ h0) {
    int idx = blockIdx.x * blockDim.x + threadIdx.x;
    if (idx < 2 * T_) d_bar[idx]  = 0u;
    if (idx < 2048)   d_wsum[idx] = 0.f;
    if (idx < B_ * 1024) {
        int b = idx >> 10, hcol = idx & 1023;
        float v = h0[idx];
        __nv_bfloat16 hi = __float2bfloat16_rn(v);
        __nv_bfloat16 lo = __float2bfloat16_rn(v - __bfloat162float(hi));
        int fi = hfrag_idx(b, hcol);
        d_hfrag[0][0][fi] = __bfloat16_as_ushort(hi);
        d_hfrag[0][1][fi] = __bfloat16_as_ushort(lo);
    }
}

// ---------------- wsum: column sums of w_hh ----------------
__global__ void __launch_bounds__(256) wsum_kernel(const float* __restrict__ w_hh) {
    int k  = blockIdx.x * 256 + threadIdx.x;
    int j0 = blockIdx.y * 256;
    float s = 0.f;
#pragma unroll 4
    for (int j = 0; j < 256; j++) s += w_hh[(size_t)(j0 + j) * 1024 + k];
    atomicAdd(&d_wsum[(j0 >= 2048 ? 1024 : 0) + k], s);
}

// ---------------- fp32 -> bf16 hi/lo split ----------------
__global__ void __launch_bounds__(256) split_kernel(const float* __restrict__ src,
                                                    __nv_bfloat16* __restrict__ hi,
                                                    __nv_bfloat16* __restrict__ lo, int n4) {
    int i = blockIdx.x * blockDim.x + threadIdx.x;
    if (i >= n4) return;
    float4 v = ((const float4*)src)[i];
    uint2 h, l;
    split4(v, h, l);
    ((uint2*)hi)[i] = h;
    ((uint2*)lo)[i] = l;
}

// ---------------- Phase A: bf16 mma.sync GEMM, 2-way split (unchanged) ----------------
#define ASTR        80
#define TILE_BYTES  (128 * ASTR)
#define STAGE_BYTES (4 * TILE_BYTES)
#define SMEM_GEMM   (2 * STAGE_BYTES)

__global__ void __launch_bounds__(256, 1) gemm_mma() {
    extern __shared__ __align__(16) char sm[];
    uint32_t sb = smem_u32(sm);
    const int tid = threadIdx.x, wid = tid >> 5, lane = tid & 31;
    const int m0 = blockIdx.y * 128, n0 = blockIdx.x * 128;
    const int wm = wid >> 2, wn = wid & 3;

    auto load_stage = [&](int c, int st) {
        uint32_t dst0 = sb + st * STAGE_BYTES;
        int kofs = c * 32;
#pragma unroll
        for (int t = 0; t < 8; t++) {
            int tile = t >> 1;
            int row  = ((t & 1) << 6) + (tid >> 2);
            int seg  = tid & 3;
            uint32_t dst = dst0 + tile * TILE_BYTES + row * ASTR + seg * 16;
            const __nv_bfloat16* src;
            if      (tile == 0) src = d_xhi + (size_t)(m0 + row) * 1024 + kofs + seg * 8;
            else if (tile == 1) src = d_xlo + (size_t)(m0 + row) * 1024 + kofs + seg * 8;
            else if (tile == 2) src = d_whi + (size_t)(n0 + row) * 1024 + kofs + seg * 8;
            else                src = d_wlo + (size_t)(n0 + row) * 1024 + kofs + seg * 8;
            CP_ASYNC(dst, (uint64_t)__cvta_generic_to_global(src));
        }
    };

    float acc[4][4][4];
#pragma unroll
    for (int i = 0; i < 4; i++)
#pragma unroll
        for (int j = 0; j < 4; j++)
#pragma unroll
            for (int k = 0; k < 4; k++) acc[i][j][k] = 0.f;

    load_stage(0, 0);
    CP_COMMIT();

    for (int c = 0; c < 32; c++) {
        int b = c & 1;
        if (c < 31) { load_stage(c + 1, b ^ 1); CP_COMMIT(); CP_WAIT1(); }
        else        { CP_WAIT0(); }
        __syncthreads();

        uint32_t base = sb + b * STAGE_BYTES;
#pragma unroll
        for (int s = 0; s < 2; s++) {
            uint32_t ah[4][4], al[4][4], bh[4][2], bl[4][2];
            uint32_t ak = s * 32 + ((lane >> 4) << 4);
#pragma unroll
            for (int mi = 0; mi < 4; mi++) {
                uint32_t ra = base + (wm * 64 + mi * 16 + (lane & 15)) * ASTR + ak;
                ldsm_x4(ah[mi], ra);
                ldsm_x4(al[mi], ra + TILE_BYTES);
            }
            uint32_t bk = s * 32 + (((lane >> 3) & 1) << 4);
#pragma unroll
            for (int ni = 0; ni < 4; ni++) {
                uint32_t rb = base + 2 * TILE_BYTES + (wn * 32 + ni * 8 + (lane & 7)) * ASTR + bk;
                ldsm_x2(bh[ni], rb);
                ldsm_x2(bl[ni], rb + TILE_BYTES);
            }
#pragma unroll
            for (int mi = 0; mi < 4; mi++)
#pragma unroll
                for (int ni = 0; ni < 4; ni++) {
                    mma_bf16(acc[mi][ni], ah[mi], bh[ni]);
                    mma_bf16(acc[mi][ni], ah[mi], bl[ni]);
                    mma_bf16(acc[mi][ni], al[mi], bh[ni]);
                }
        }
        __syncthreads();
    }

    int g = lane >> 2, q = lane & 3;
#pragma unroll
    for (int mi = 0; mi < 4; mi++) {
        int r0 = m0 + wm * 64 + mi * 16 + g;
#pragma unroll
        for (int ni = 0; ni < 4; ni++) {
            int cc = n0 + wn * 32 + ni * 8 + q * 2;
            *(float2*)(d_proj + (size_t)r0 * 3072 + cc)       = make_float2(acc[mi][ni][0], acc[mi][ni][1]);
            *(float2*)(d_proj + (size_t)(r0 + 8) * 3072 + cc) = make_float2(acc[mi][ni][2], acc[mi][ni][3]);
        }
    }
}

// ---------------- block reduce helper ----------------
__device__ __forceinline__ float2 block_reduce2(float s, float s2, float* sm) {
#pragma unroll
    for (int o = 16; o; o >>= 1) {
        s  += __shfl_down_sync(0xffffffffu, s,  o);
        s2 += __shfl_down_sync(0xffffffffu, s2, o);
    }
    int w = threadIdx.x >> 5, l = threadIdx.x & 31;
    if (l == 0) { sm[w] = s; sm[8 + w] = s2; }
    __syncthreads();
    if (threadIdx.x < 32) {
        s  = (l < 8) ? sm[l]     : 0.f;
        s2 = (l < 8) ? sm[8 + l] : 0.f;
#pragma unroll
        for (int o = 4; o; o >>= 1) {
            s  += __shfl_down_sync(0xffffffffu, s,  o);
            s2 += __shfl_down_sync(0xffffffffu, s2, o);
        }
        if (l == 0) { sm[16] = s; sm[17] = s2; }
    }
    __syncthreads();
    return make_float2(sm[16], sm[17]);
}

// ---------------- Phase B: LN_x in place ----------------
__global__ void __launch_bounds__(256) ln_x_kernel(const float* __restrict__ gamma,
                                                   const float* __restrict__ beta) {
    __shared__ float sm[18];
    float* row = d_proj + (size_t)blockIdx.x * 3072;
    const int tid = threadIdx.x;

    float v[8];
    float s = 0.f, s2 = 0.f;
#pragma unroll
    for (int i = 0; i < 8; i++) {
        float x = row[tid + (i << 8)];
        v[i] = x; s += x; s2 += x * x;
    }
    float2 r = block_reduce2(s, s2, sm);
    {
        float mean = r.x * (1.f / 2048.f);
        float var  = (r.y - 2048.f * mean * mean) * (1.f / 2047.f);
        float rstd = rsqrtf(var);
#pragma unroll
        for (int i = 0; i < 8; i++) {
            int c = tid + (i << 8);
            row[c] = gamma[c] * (v[i] - mean) * rstd + beta[c];
        }
    }
    __syncthreads();

    float vn[4];
    s = 0.f; s2 = 0.f;
#pragma unroll
    for (int i = 0; i < 4; i++) {
        float x = row[2048 + tid + (i << 8)];
        vn[i] = x; s += x; s2 += x * x;
    }
    r = block_reduce2(s, s2, sm);
    {
        float mean = r.x * (1.f / 1024.f);
        float var  = (r.y - 1024.f * mean * mean) * (1.f / 1023.f);
        float rstd = rsqrtf(var);
#pragma unroll
        for (int i = 0; i < 4; i++) {
            int c = 2048 + tid + (i << 8);
            row[c] = gamma[c] * (vn[i] - mean) * rstd + beta[c];
        }
    }
}

// ---------------- grid barrier (no nanosleep — tight poll) ----------------
__device__ __forceinline__ void grid_barrier(int k) {
    __syncthreads();
    if (threadIdx.x == 0) {
        __threadfence();
        unsigned arrived = atomicAdd(&d_bar[k], 1u) + 1u;
        if (arrived < NCTA) {
            volatile unsigned* p = &d_bar[k];
            while (*p < NCTA) { }
        }
    }
    __syncthreads();
}

// ---------------- Phase C: persistent recurrent kernel, fragment-direct h ----------------
// CTA i owns output columns j = i*8 .. i*8+7 across all three gates.
// B tile (32 rows): [0..7]=w_r, [8..15]=w_z, [16..23]=w_n, 24=wsum_rz, 25=wsum_n, 26..31=0.
#define WSB      2064
#define OFF_WHI  0
#define OFF_WLO  66048
#define OFF_RED  132096      // 8 warps x 512 floats
#define OFF_FIN  148480      // 512 floats
#define SMEM_REC 150528

__global__ void __launch_bounds__(256, 1) gru_rec(const float* __restrict__ w_hh,
                                                  const float* __restrict__ b_hh,
                                                  const float* __restrict__ gamma_hh,
                                                  const float* __restrict__ h0,
                                                  float* __restrict__ out) {
    extern __shared__ __align__(16) char sm[];
    uint32_t sb = smem_u32(sm);
    float* red = (float*)(sm + OFF_RED);
    float* fin = (float*)(sm + OFF_FIN);

    const int cta  = blockIdx.x;
    const int tid  = threadIdx.x;
    const int j0   = cta * 8;
    const int warp = tid >> 5, lane = tid & 31;

    // --- startup: stage own w rows (24) + wsum rows (2), zero rows 26..31 ---
    for (int i = tid; i < 24 * 256; i += 256) {
        int c  = i >> 8;
        int kq = (i & 255) << 2;
        int src_row = (c >> 3) * 1024 + j0 + (c & 7);
        float4 v = *(const float4*)(w_hh + (size_t)src_row * 1024 + kq);
        uint2 hi, lo;
        split4(v, hi, lo);
        *(uint2*)(sm + OFF_WHI + c * WSB + kq * 2) = hi;
        *(uint2*)(sm + OFF_WLO + c * WSB + kq * 2) = lo;
    }
    for (int i = tid; i < 2 * 256; i += 256) {
        int c  = i >> 8;
        int kq = (i & 255) << 2;
        float4 v = *(const float4*)(d_wsum + c * 1024 + kq);
        uint2 hi, lo;
        split4(v, hi, lo);
        *(uint2*)(sm + OFF_WHI + (24 + c) * WSB + kq * 2) = hi;
        *(uint2*)(sm + OFF_WLO + (24 + c) * WSB + kq * 2) = lo;
    }
    for (int i = tid; i < 6 * 129; i += 256) {
        int r = 26 + i / 129, seg = i % 129;
        *(uint4*)(sm + OFF_WHI + r * WSB + seg * 16) = make_uint4(0, 0, 0, 0);
        *(uint4*)(sm + OFF_WLO + r * WSB + seg * 16) = make_uint4(0, 0, 0, 0);
    }

    // per-thread constants for the update phase
    const int ub = tid >> 3, uj = tid & 7;
    const int jg = j0 + uj;
    float g_r = 0, g_z = 0, g_n = 0, bb_r = 0, bb_z = 0, bb_n = 0, h_prev = 0;
    int fidx = 0;
    if (tid < 128) {
        g_r  = gamma_hh[jg];        bb_r = b_hh[jg];
        g_z  = gamma_hh[1024 + jg]; bb_z = b_hh[1024 + jg];
        g_n  = gamma_hh[2048 + jg]; bb_n = b_hh[2048 + jg];
        h_prev = h0[ub * 1024 + jg];
        fidx = hfrag_idx(ub, jg);
    }
    __syncthreads();

    const uint32_t wb_base = sb + OFF_WHI + (lane & 7) * WSB + warp * 256 + (((lane >> 3) & 1) << 4);
    const int g = lane >> 2, q = lane & 3;
    const int fbase = warp * 8 * 32 + lane;          // uint4 index for kstep 0 of this warp

    for (int t = 0; t < T_; t++) {
        // prefetch x row entries (not barrier-protected)
        float x_r = 0.f, x_z = 0.f, x_n = 0.f;
        if (tid < 128) {
            const float* xr = d_proj + ((size_t)ub * T_ + t) * 3072;
            x_r = xr[jg]; x_z = xr[1024 + jg]; x_n = xr[2048 + jg];
        }

        // load A fragments of h directly from global (fragment layout, L1-bypass)
        const uint4* fh = (const uint4*)d_hfrag[t & 1][0];
        const uint4* fl = (const uint4*)d_hfrag[t & 1][1];
        uint4 AH[8], AL[8];
#pragma unroll
        for (int s = 0; s < 8; s++) {
            AH[s] = __ldcg(fh + fbase + s * 32);
            AL[s] = __ldcg(fl + fbase + s * 32);
        }

        float acc[4][4];
#pragma unroll
        for (int ni = 0; ni < 4; ni++)
#pragma unroll
            for (int j = 0; j < 4; j++) acc[ni][j] = 0.f;

#pragma unroll
        for (int s = 0; s < 8; s++) {
#pragma unroll
            for (int ni = 0; ni < 4; ni++) {
                uint32_t wb = wb_base + ni * 8 * WSB + s * 32;
                uint32_t bhf[2], blf[2];
                ldsm_x2(bhf, wb);
                ldsm_x2(blf, wb + (OFF_WLO - OFF_WHI));
                mma_bf16(acc[ni], (const uint32_t*)&AH[s], bhf);
                mma_bf16(acc[ni], (const uint32_t*)&AH[s], blf);
                mma_bf16(acc[ni], (const uint32_t*)&AL[s], bhf);
            }
        }
        float* rp = red + warp * 512;
#pragma unroll
        for (int ni = 0; ni < 4; ni++) {
            int col = ni * 8 + q * 2;
            rp[g * 32 + col]           = acc[ni][0];
            rp[g * 32 + col + 1]       = acc[ni][1];
            rp[(g + 8) * 32 + col]     = acc[ni][2];
            rp[(g + 8) * 32 + col + 1] = acc[ni][3];
        }
        __syncthreads();

        // cross-warp reduce into fin[b*32 + col]
        for (int o = tid; o < 512; o += 256) {
            float s = 0.f;
#pragma unroll
            for (int w = 0; w < 8; w++) s += red[w * 512 + o];
            fin[o] = s;
        }
        __syncthreads();

        // fully local gate + state update; write h into fragment layout
        if (tid < 128) {
            const float* fb = fin + ub * 32;
            float mrz = fb[24] * (1.f / 2048.f);
            float mn  = fb[25] * (1.f / 1024.f);
            float lnr = g_r * (fb[uj]      - mrz) + bb_r;
            float lnz = g_z * (fb[8 + uj]  - mrz) + bb_z;
            float lnn = g_n * (fb[16 + uj] - mn)  + bb_n;
            float rg  = 1.f / (1.f + expf(-(x_r + lnr)));
            float zg  = 1.f / (1.f + expf(-(x_z + lnz)));
            float ng  = tanhf(x_n + rg * lnn);
            float hnew = (1.f - zg) * ng + zg * h_prev;
            h_prev = hnew;
            size_t bt = (size_t)ub * T_ + t;
            out[bt * 1024 + jg] = hnew;
            if (t == T_ - 1) out[(size_t)B_ * T_ * 1024 + ub * 1024 + jg] = hnew;
            __nv_bfloat16 hi = __float2bfloat16_rn(hnew);
            __nv_bfloat16 lo = __float2bfloat16_rn(hnew - __bfloat162float(hi));
            d_hfrag[(t + 1) & 1][0][fidx] = __bfloat16_as_ushort(hi);
            d_hfrag[(t + 1) & 1][1][fidx] = __bfloat16_as_ushort(lo);
        }
        grid_barrier(t);
    }
}

// ---------------- launch ----------------
extern "C" void kernel_launch(void* const* d_in, const int* in_sizes, int n_in,
                              void* d_out, int out_size) {
    const float* xs   = (const float*)d_in[0];
    const float* h0   = (const float*)d_in[1];
    const float* w_ih = (const float*)d_in[2];
    const float* w_hh = (const float*)d_in[3];
    const float* b_ih = (const float*)d_in[4];
    const float* b_hh = (const float*)d_in[5];
    const float* g_ih = (const float*)d_in[6];
    const float* g_hh = (const float*)d_in[7];
    float* out = (float*)d_out;

    cudaFuncSetAttribute(gru_rec,  cudaFuncAttributeMaxDynamicSharedMemorySize, SMEM_REC);
    cudaFuncSetAttribute(gemm_mma, cudaFuncAttributeMaxDynamicSharedMemorySize, SMEM_GEMM);

    init_kernel<<<256, 256>>>(h0);

    dim3 wg(4, 12);
    wsum_kernel<<<wg, 256>>>(w_hh);

    __nv_bfloat16 *xhi_p, *xlo_p, *whi_p, *wlo_p;
    cudaGetSymbolAddress((void**)&xhi_p, d_xhi);
    cudaGetSymbolAddress((void**)&xlo_p, d_xlo);
    cudaGetSymbolAddress((void**)&whi_p, d_whi);
    cudaGetSymbolAddress((void**)&wlo_p, d_wlo);
    split_kernel<<<(33554432 / 4 + 255) / 256, 256>>>(xs, xhi_p, xlo_p, 33554432 / 4);
    split_kernel<<<(3145728 / 4 + 255) / 256, 256>>>(w_ih, whi_p, wlo_p, 3145728 / 4);

    dim3 g(G_ / 128, 32768 / 128);
    gemm_mma<<<g, 256, SMEM_GEMM>>>();

    ln_x_kernel<<<16 * 2048, 256>>>(g_ih, b_ih);
    gru_rec<<<NCTA, 256, SMEM_REC>>>(w_hh, b_hh, g_hh, h0, out);
}

// round 6
// speedup vs baseline: 3.7682x; 1.2294x over previous
#include <cuda_runtime.h>
#include <cuda_bf16.h>
#include <cuda_fp16.h>
#include <cstdint>

#define B_   16
#define T_   2048
#define G_   3072
#define NCTA 128

// ---------------- scratch (static device memory; no allocation) ----------------
__device__ float         d_proj[100663296ULL];   // 32768 x 3072 fp32
__device__ float         d_wsum[2048];           // [rz | n] column sums of w_hh
__device__ unsigned int  d_bar[2 * T_];
// hidden state in m16n8k16 A-fragment order, single fp16 plane
__device__ __align__(16) unsigned short d_hfrag[2][32768];
__device__ __nv_bfloat16 d_xhi[33554432];
__device__ __nv_bfloat16 d_xlo[33554432];
__device__ __nv_bfloat16 d_whi[3145728];
__device__ __nv_bfloat16 d_wlo[3145728];

// ================= helpers =================
__device__ __forceinline__ uint32_t smem_u32(const void* p) {
    uint32_t a;
    asm("{ .reg .u64 t; cvta.to.shared.u64 t, %1; cvt.u32.u64 %0, t; }" : "=r"(a) : "l"(p));
    return a;
}
__device__ __forceinline__ void ldsm_x4(uint32_t* r, uint32_t addr) {
    asm volatile("ldmatrix.sync.aligned.m8n8.x4.shared.b16 {%0,%1,%2,%3}, [%4];"
                 : "=r"(r[0]), "=r"(r[1]), "=r"(r[2]), "=r"(r[3]) : "r"(addr));
}
__device__ __forceinline__ void ldsm_x2(uint32_t* r, uint32_t addr) {
    asm volatile("ldmatrix.sync.aligned.m8n8.x2.shared.b16 {%0,%1}, [%2];"
                 : "=r"(r[0]), "=r"(r[1]) : "r"(addr));
}
__device__ __forceinline__ void mma_bf16(float* d, const uint32_t* a, const uint32_t* b) {
    asm volatile("mma.sync.aligned.m16n8k16.row.col.f32.bf16.bf16.f32 "
                 "{%0,%1,%2,%3}, {%4,%5,%6,%7}, {%8,%9}, {%0,%1,%2,%3};"
                 : "+f"(d[0]), "+f"(d[1]), "+f"(d[2]), "+f"(d[3])
                 : "r"(a[0]), "r"(a[1]), "r"(a[2]), "r"(a[3]), "r"(b[0]), "r"(b[1]));
}
__device__ __forceinline__ void mma_f16(float* d, const uint32_t* a, const uint32_t* b) {
    asm volatile("mma.sync.aligned.m16n8k16.row.col.f32.f16.f16.f32 "
                 "{%0,%1,%2,%3}, {%4,%5,%6,%7}, {%8,%9}, {%0,%1,%2,%3};"
                 : "+f"(d[0]), "+f"(d[1]), "+f"(d[2]), "+f"(d[3])
                 : "r"(a[0]), "r"(a[1]), "r"(a[2]), "r"(a[3]), "r"(b[0]), "r"(b[1]));
}
#define CP_ASYNC(dst, src) \
    asm volatile("cp.async.ca.shared.global [%0], [%1], 16;" :: "r"(dst), "l"(src) : "memory")
#define CP_COMMIT() asm volatile("cp.async.commit_group;" ::: "memory")
#define CP_WAIT1()  asm volatile("cp.async.wait_group 1;" ::: "memory")
#define CP_WAIT0()  asm volatile("cp.async.wait_group 0;" ::: "memory")

__device__ __forceinline__ void split4(float4 v, uint2& hi, uint2& lo) {
    __nv_bfloat16 h0 = __float2bfloat16_rn(v.x), h1 = __float2bfloat16_rn(v.y);
    __nv_bfloat16 h2 = __float2bfloat16_rn(v.z), h3 = __float2bfloat16_rn(v.w);
    __nv_bfloat16 l0 = __float2bfloat16_rn(v.x - __bfloat162float(h0));
    __nv_bfloat16 l1 = __float2bfloat16_rn(v.y - __bfloat162float(h1));
    __nv_bfloat16 l2 = __float2bfloat16_rn(v.z - __bfloat162float(h2));
    __nv_bfloat16 l3 = __float2bfloat16_rn(v.w - __bfloat162float(h3));
    hi.x = (uint32_t)__bfloat16_as_ushort(h0) | ((uint32_t)__bfloat16_as_ushort(h1) << 16);
    hi.y = (uint32_t)__bfloat16_as_ushort(h2) | ((uint32_t)__bfloat16_as_ushort(h3) << 16);
    lo.x = (uint32_t)__bfloat16_as_ushort(l0) | ((uint32_t)__bfloat16_as_ushort(l1) << 16);
    lo.y = (uint32_t)__bfloat16_as_ushort(l2) | ((uint32_t)__bfloat16_as_ushort(l3) << 16);
}
__device__ __forceinline__ uint2 f4_to_h4(float4 v) {
    __half2 a = __floats2half2_rn(v.x, v.y);
    __half2 b = __floats2half2_rn(v.z, v.w);
    uint2 r;
    r.x = *(uint32_t*)&a;
    r.y = *(uint32_t*)&b;
    return r;
}

// A-fragment u16 index for h element (b, hcol), m16n8k16 layout
__device__ __forceinline__ int hfrag_idx(int b, int hcol) {
    int kg    = hcol >> 4;
    int col16 = hcol & 15;
    int lane  = (b & 7) * 4 + ((col16 >> 1) & 3);
    int reg   = ((col16 >> 3) << 1) | (b >> 3);
    return (((kg * 32 + lane) << 2) + reg) * 2 + (col16 & 1);
}

// ---------------- init: zero barriers + wsum, write h0 into fragment layout ----------------
__global__ void __launch_bounds__(256) init_kernel(const float* __restrict__ h0) {
    int idx = blockIdx.x * blockDim.x + threadIdx.x;
    if (idx < 2 * T_) d_bar[idx]  = 0u;
    if (idx < 2048)   d_wsum[idx] = 0.f;
    if (idx < B_ * 1024) {
        int b = idx >> 10, hcol = idx & 1023;
        __half hv = __float2half_rn(h0[idx]);
        d_hfrag[0][hfrag_idx(b, hcol)] = *(unsigned short*)&hv;
    }
}

// ---------------- wsum: column sums of w_hh ----------------
__global__ void __launch_bounds__(256) wsum_kernel(const float* __restrict__ w_hh) {
    int k  = blockIdx.x * 256 + threadIdx.x;
    int j0 = blockIdx.y * 256;
    float s = 0.f;
#pragma unroll 4
    for (int j = 0; j < 256; j++) s += w_hh[(size_t)(j0 + j) * 1024 + k];
    atomicAdd(&d_wsum[(j0 >= 2048 ? 1024 : 0) + k], s);
}

// ---------------- fp32 -> bf16 hi/lo split ----------------
__global__ void __launch_bounds__(256) split_kernel(const float* __restrict__ src,
                                                    __nv_bfloat16* __restrict__ hi,
                                                    __nv_bfloat16* __restrict__ lo, int n4) {
    int i = blockIdx.x * blockDim.x + threadIdx.x;
    if (i >= n4) return;
    float4 v = ((const float4*)src)[i];
    uint2 h, l;
    split4(v, h, l);
    ((uint2*)hi)[i] = h;
    ((uint2*)lo)[i] = l;
}

// ---------------- Phase A: bf16 mma.sync GEMM, 2-way split (unchanged) ----------------
#define ASTR        80
#define TILE_BYTES  (128 * ASTR)
#define STAGE_BYTES (4 * TILE_BYTES)
#define SMEM_GEMM   (2 * STAGE_BYTES)

__global__ void __launch_bounds__(256, 1) gemm_mma() {
    extern __shared__ __align__(16) char sm[];
    uint32_t sb = smem_u32(sm);
    const int tid = threadIdx.x, wid = tid >> 5, lane = tid & 31;
    const int m0 = blockIdx.y * 128, n0 = blockIdx.x * 128;
    const int wm = wid >> 2, wn = wid & 3;

    auto load_stage = [&](int c, int st) {
        uint32_t dst0 = sb + st * STAGE_BYTES;
        int kofs = c * 32;
#pragma unroll
        for (int t = 0; t < 8; t++) {
            int tile = t >> 1;
            int row  = ((t & 1) << 6) + (tid >> 2);
            int seg  = tid & 3;
            uint32_t dst = dst0 + tile * TILE_BYTES + row * ASTR + seg * 16;
            const __nv_bfloat16* src;
            if      (tile == 0) src = d_xhi + (size_t)(m0 + row) * 1024 + kofs + seg * 8;
            else if (tile == 1) src = d_xlo + (size_t)(m0 + row) * 1024 + kofs + seg * 8;
            else if (tile == 2) src = d_whi + (size_t)(n0 + row) * 1024 + kofs + seg * 8;
            else                src = d_wlo + (size_t)(n0 + row) * 1024 + kofs + seg * 8;
            CP_ASYNC(dst, (uint64_t)__cvta_generic_to_global(src));
        }
    };

    float acc[4][4][4];
#pragma unroll
    for (int i = 0; i < 4; i++)
#pragma unroll
        for (int j = 0; j < 4; j++)
#pragma unroll
            for (int k = 0; k < 4; k++) acc[i][j][k] = 0.f;

    load_stage(0, 0);
    CP_COMMIT();

    for (int c = 0; c < 32; c++) {
        int b = c & 1;
        if (c < 31) { load_stage(c + 1, b ^ 1); CP_COMMIT(); CP_WAIT1(); }
        else        { CP_WAIT0(); }
        __syncthreads();

        uint32_t base = sb + b * STAGE_BYTES;
#pragma unroll
        for (int s = 0; s < 2; s++) {
            uint32_t ah[4][4], al[4][4], bh[4][2], bl[4][2];
            uint32_t ak = s * 32 + ((lane >> 4) << 4);
#pragma unroll
            for (int mi = 0; mi < 4; mi++) {
                uint32_t ra = base + (wm * 64 + mi * 16 + (lane & 15)) * ASTR + ak;
                ldsm_x4(ah[mi], ra);
                ldsm_x4(al[mi], ra + TILE_BYTES);
            }
            uint32_t bk = s * 32 + (((lane >> 3) & 1) << 4);
#pragma unroll
            for (int ni = 0; ni < 4; ni++) {
                uint32_t rb = base + 2 * TILE_BYTES + (wn * 32 + ni * 8 + (lane & 7)) * ASTR + bk;
                ldsm_x2(bh[ni], rb);
                ldsm_x2(bl[ni], rb + TILE_BYTES);
            }
#pragma unroll
            for (int mi = 0; mi < 4; mi++)
#pragma unroll
                for (int ni = 0; ni < 4; ni++) {
                    mma_bf16(acc[mi][ni], ah[mi], bh[ni]);
                    mma_bf16(acc[mi][ni], ah[mi], bl[ni]);
                    mma_bf16(acc[mi][ni], al[mi], bh[ni]);
                }
        }
        __syncthreads();
    }

    int g = lane >> 2, q = lane & 3;
#pragma unroll
    for (int mi = 0; mi < 4; mi++) {
        int r0 = m0 + wm * 64 + mi * 16 + g;
#pragma unroll
        for (int ni = 0; ni < 4; ni++) {
            int cc = n0 + wn * 32 + ni * 8 + q * 2;
            *(float2*)(d_proj + (size_t)r0 * 3072 + cc)       = make_float2(acc[mi][ni][0], acc[mi][ni][1]);
            *(float2*)(d_proj + (size_t)(r0 + 8) * 3072 + cc) = make_float2(acc[mi][ni][2], acc[mi][ni][3]);
        }
    }
}

// ---------------- block reduce helper ----------------
__device__ __forceinline__ float2 block_reduce2(float s, float s2, float* sm) {
#pragma unroll
    for (int o = 16; o; o >>= 1) {
        s  += __shfl_down_sync(0xffffffffu, s,  o);
        s2 += __shfl_down_sync(0xffffffffu, s2, o);
    }
    int w = threadIdx.x >> 5, l = threadIdx.x & 31;
    if (l == 0) { sm[w] = s; sm[8 + w] = s2; }
    __syncthreads();
    if (threadIdx.x < 32) {
        s  = (l < 8) ? sm[l]     : 0.f;
        s2 = (l < 8) ? sm[8 + l] : 0.f;
#pragma unroll
        for (int o = 4; o; o >>= 1) {
            s  += __shfl_down_sync(0xffffffffu, s,  o);
            s2 += __shfl_down_sync(0xffffffffu, s2, o);
        }
        if (l == 0) { sm[16] = s; sm[17] = s2; }
    }
    __syncthreads();
    return make_float2(sm[16], sm[17]);
}

// ---------------- Phase B: LN_x in place ----------------
__global__ void __launch_bounds__(256) ln_x_kernel(const float* __restrict__ gamma,
                                                   const float* __restrict__ beta) {
    __shared__ float sm[18];
    float* row = d_proj + (size_t)blockIdx.x * 3072;
    const int tid = threadIdx.x;

    float v[8];
    float s = 0.f, s2 = 0.f;
#pragma unroll
    for (int i = 0; i < 8; i++) {
        float x = row[tid + (i << 8)];
        v[i] = x; s += x; s2 += x * x;
    }
    float2 r = block_reduce2(s, s2, sm);
    {
        float mean = r.x * (1.f / 2048.f);
        float var  = (r.y - 2048.f * mean * mean) * (1.f / 2047.f);
        float rstd = rsqrtf(var);
#pragma unroll
        for (int i = 0; i < 8; i++) {
            int c = tid + (i << 8);
            row[c] = gamma[c] * (v[i] - mean) * rstd + beta[c];
        }
    }
    __syncthreads();

    float vn[4];
    s = 0.f; s2 = 0.f;
#pragma unroll
    for (int i = 0; i < 4; i++) {
        float x = row[2048 + tid + (i << 8)];
        vn[i] = x; s += x; s2 += x * x;
    }
    r = block_reduce2(s, s2, sm);
    {
        float mean = r.x * (1.f / 1024.f);
        float var  = (r.y - 1024.f * mean * mean) * (1.f / 1023.f);
        float rstd = rsqrtf(var);
#pragma unroll
        for (int i = 0; i < 4; i++) {
            int c = 2048 + tid + (i << 8);
            row[c] = gamma[c] * (vn[i] - mean) * rstd + beta[c];
        }
    }
}

// ---------------- grid barrier ----------------
__device__ __forceinline__ void grid_barrier(int k) {
    __syncthreads();
    if (threadIdx.x == 0) {
        __threadfence();
        unsigned arrived = atomicAdd(&d_bar[k], 1u) + 1u;
        if (arrived < NCTA) {
            volatile unsigned* p = &d_bar[k];
            while (*p < NCTA) { }
        }
    }
    __syncthreads();
}

// ---------------- Phase C: persistent recurrent kernel, fp16 single product ----------------
// CTA i owns output columns j = i*8 .. i*8+7 across all three gates.
// B tile (32 rows): [0..7]=w_r, [8..15]=w_z, [16..23]=w_n, 24=wsum_rz, 25=wsum_n, 26..31=0.
#define WSB      2064
#define OFF_W    0                 // 32 rows x 2064 B fp16
#define OFF_RED  66048             // 8 warps x 512 floats
#define OFF_FIN  82432             // 512 floats
#define SMEM_REC 84480

__global__ void __launch_bounds__(256, 1) gru_rec(const float* __restrict__ w_hh,
                                                  const float* __restrict__ b_hh,
                                                  const float* __restrict__ gamma_hh,
                                                  const float* __restrict__ h0,
                                                  float* __restrict__ out) {
    extern __shared__ __align__(16) char sm[];
    uint32_t sb = smem_u32(sm);
    float* red = (float*)(sm + OFF_RED);
    float* fin = (float*)(sm + OFF_FIN);

    const int cta  = blockIdx.x;
    const int tid  = threadIdx.x;
    const int j0   = cta * 8;
    const int warp = tid >> 5, lane = tid & 31;

    // --- startup: stage w rows (24) + wsum rows (2) as fp16; zero rows 26..31 ---
    for (int i = tid; i < 24 * 256; i += 256) {
        int c  = i >> 8;
        int kq = (i & 255) << 2;
        int src_row = (c >> 3) * 1024 + j0 + (c & 7);
        float4 v = *(const float4*)(w_hh + (size_t)src_row * 1024 + kq);
        *(uint2*)(sm + OFF_W + c * WSB + kq * 2) = f4_to_h4(v);
    }
    for (int i = tid; i < 2 * 256; i += 256) {
        int c  = i >> 8;
        int kq = (i & 255) << 2;
        float4 v = *(const float4*)(d_wsum + c * 1024 + kq);
        *(uint2*)(sm + OFF_W + (24 + c) * WSB + kq * 2) = f4_to_h4(v);
    }
    for (int i = tid; i < 6 * 129; i += 256) {
        int r = 26 + i / 129, seg = i % 129;
        *(uint4*)(sm + OFF_W + r * WSB + seg * 16) = make_uint4(0, 0, 0, 0);
    }

    // per-thread constants for the update phase
    const int ub = tid >> 3, uj = tid & 7;
    const int jg = j0 + uj;
    float g_r = 0, g_z = 0, g_n = 0, bb_r = 0, bb_z = 0, bb_n = 0, h_prev = 0;
    int fidx = 0;
    if (tid < 128) {
        g_r  = gamma_hh[jg];        bb_r = b_hh[jg];
        g_z  = gamma_hh[1024 + jg]; bb_z = b_hh[1024 + jg];
        g_n  = gamma_hh[2048 + jg]; bb_n = b_hh[2048 + jg];
        h_prev = h0[ub * 1024 + jg];
        fidx = hfrag_idx(ub, jg);
    }
    __syncthreads();

    // --- hoist ALL B fragments into registers (w is stationary) ---
    const uint32_t wb_base = sb + OFF_W + (lane & 7) * WSB + warp * 256 + (((lane >> 3) & 1) << 4);
    uint32_t Bf[8][4][2];
#pragma unroll
    for (int s = 0; s < 8; s++)
#pragma unroll
        for (int ni = 0; ni < 4; ni++)
            ldsm_x2(Bf[s][ni], wb_base + ni * 8 * WSB + s * 32);

    const int g = lane >> 2, q = lane & 3;
    const int fbase = warp * 8 * 32 + lane;          // uint4 index for kstep 0 of this warp

    // prefetch x for t = 0
    float x_r = 0.f, x_z = 0.f, x_n = 0.f;
    if (tid < 128) {
        const float* xr = d_proj + (size_t)ub * T_ * 3072;
        x_r = xr[jg]; x_z = xr[1024 + jg]; x_n = xr[2048 + jg];
    }

    for (int t = 0; t < T_; t++) {
        // load A fragments of h directly from global (fragment layout, L1-bypass)
        const uint4* fh = (const uint4*)d_hfrag[t & 1];
        uint4 AH[8];
#pragma unroll
        for (int s = 0; s < 8; s++) AH[s] = __ldcg(fh + fbase + s * 32);

        float acc[4][4];
#pragma unroll
        for (int ni = 0; ni < 4; ni++)
#pragma unroll
            for (int j = 0; j < 4; j++) acc[ni][j] = 0.f;

#pragma unroll
        for (int s = 0; s < 8; s++)
#pragma unroll
            for (int ni = 0; ni < 4; ni++)
                mma_f16(acc[ni], (const uint32_t*)&AH[s], Bf[s][ni]);

        float* rp = red + warp * 512;
#pragma unroll
        for (int ni = 0; ni < 4; ni++) {
            int col = ni * 8 + q * 2;
            rp[g * 32 + col]           = acc[ni][0];
            rp[g * 32 + col + 1]       = acc[ni][1];
            rp[(g + 8) * 32 + col]     = acc[ni][2];
            rp[(g + 8) * 32 + col + 1] = acc[ni][3];
        }
        __syncthreads();

        // cross-warp reduce into fin[b*32 + col]
        for (int o = tid; o < 512; o += 256) {
            float s = 0.f;
#pragma unroll
            for (int w = 0; w < 8; w++) s += red[w * 512 + o];
            fin[o] = s;
        }
        __syncthreads();

        // fully local gate + state update; write h into fragment layout (fp16)
        if (tid < 128) {
            const float* fb = fin + ub * 32;
            float mrz = fb[24] * (1.f / 2048.f);
            float mn  = fb[25] * (1.f / 1024.f);
            float lnr = g_r * (fb[uj]      - mrz) + bb_r;
            float lnz = g_z * (fb[8 + uj]  - mrz) + bb_z;
            float lnn = g_n * (fb[16 + uj] - mn)  + bb_n;
            float rg  = 1.f / (1.f + expf(-(x_r + lnr)));
            float zg  = 1.f / (1.f + expf(-(x_z + lnz)));
            float ng  = tanhf(x_n + rg * lnn);
            float hnew = (1.f - zg) * ng + zg * h_prev;
            h_prev = hnew;
            size_t bt = (size_t)ub * T_ + t;
            out[bt * 1024 + jg] = hnew;
            if (t == T_ - 1) out[(size_t)B_ * T_ * 1024 + ub * 1024 + jg] = hnew;
            __half hv = __float2half_rn(hnew);
            d_hfrag[(t + 1) & 1][fidx] = *(unsigned short*)&hv;

            // prefetch x for t+1 (hides under barrier wait)
            if (t + 1 < T_) {
                const float* xr = d_proj + ((size_t)ub * T_ + t + 1) * 3072;
                x_r = xr[jg]; x_z = xr[1024 + jg]; x_n = xr[2048 + jg];
            }
        }
        grid_barrier(t);
    }
}

// ---------------- launch ----------------
extern "C" void kernel_launch(void* const* d_in, const int* in_sizes, int n_in,
                              void* d_out, int out_size) {
    const float* xs   = (const float*)d_in[0];
    const float* h0   = (const float*)d_in[1];
    const float* w_ih = (const float*)d_in[2];
    const float* w_hh = (const float*)d_in[3];
    const float* b_ih = (const float*)d_in[4];
    const float* b_hh = (const float*)d_in[5];
    const float* g_ih = (const float*)d_in[6];
    const float* g_hh = (const float*)d_in[7];
    float* out = (float*)d_out;

    cudaFuncSetAttribute(gru_rec,  cudaFuncAttributeMaxDynamicSharedMemorySize, SMEM_REC);
    cudaFuncSetAttribute(gemm_mma, cudaFuncAttributeMaxDynamicSharedMemorySize, SMEM_GEMM);

    init_kernel<<<256, 256>>>(h0);

    dim3 wg(4, 12);
    wsum_kernel<<<wg, 256>>>(w_hh);

    __nv_bfloat16 *xhi_p, *xlo_p, *whi_p, *wlo_p;
    cudaGetSymbolAddress((void**)&xhi_p, d_xhi);
    cudaGetSymbolAddress((void**)&xlo_p, d_xlo);
    cudaGetSymbolAddress((void**)&whi_p, d_whi);
    cudaGetSymbolAddress((void**)&wlo_p, d_wlo);
    split_kernel<<<(33554432 / 4 + 255) / 256, 256>>>(xs, xhi_p, xlo_p, 33554432 / 4);
    split_kernel<<<(3145728 / 4 + 255) / 256, 256>>>(w_ih, whi_p, wlo_p, 3145728 / 4);

    dim3 g(G_ / 128, 32768 / 128);
    gemm_mma<<<g, 256, SMEM_GEMM>>>();

    ln_x_kernel<<<16 * 2048, 256>>>(g_ih, b_ih);
    gru_rec<<<NCTA, 256, SMEM_REC>>>(w_hh, b_hh, g_hh, h0, out);
}